// round 1
// baseline (speedup 1.0000x reference)
#include <cuda_runtime.h>
#include <math.h>

#define N_NODES 50000
#define N_EDGES 800000
#define NEG_SLOPE 0.2f

// ---------------- scratch (device globals; no allocation allowed) ----------------
__device__ float g_ft1[N_NODES * 256];
__device__ float g_h1 [N_NODES * 256];
__device__ float g_el1[N_NODES * 4];
__device__ float g_er1[N_NODES * 4];
__device__ float g_ft2[N_NODES * 128];
__device__ float g_el2[N_NODES];
__device__ float g_er2[N_NODES];
__device__ int   g_cnt[N_NODES];        // histogram, then reused as fill cursor
__device__ int   g_rowptr[N_NODES + 1];
__device__ int   g_colsrc[N_EDGES];     // src node id per CSR slot

// ---------------- small utils ----------------
__global__ void zero_int_kernel(int* __restrict__ p, int n) {
    for (int i = blockIdx.x * blockDim.x + threadIdx.x; i < n; i += gridDim.x * blockDim.x)
        p[i] = 0;
}

__global__ void count_dst_kernel(const int* __restrict__ dst, int* __restrict__ cnt, int E) {
    for (int e = blockIdx.x * blockDim.x + threadIdx.x; e < E; e += gridDim.x * blockDim.x)
        atomicAdd(&cnt[dst[e]], 1);
}

// single-block exclusive scan: rowptr[0]=0; rowptr[i+1]=sum(cnt[0..i])
__global__ void scan_kernel(const int* __restrict__ cnt, int* __restrict__ rowptr, int n) {
    __shared__ int warp_sums[32];
    __shared__ int s_carry;
    int tid = threadIdx.x;
    if (tid == 0) { s_carry = 0; rowptr[0] = 0; }
    __syncthreads();
    for (int base = 0; base < n; base += 1024) {
        int idx = base + tid;
        int v = (idx < n) ? cnt[idx] : 0;
        int lane = tid & 31, warp = tid >> 5;
        int x = v;
        #pragma unroll
        for (int off = 1; off < 32; off <<= 1) {
            int y = __shfl_up_sync(0xffffffffu, x, off);
            if (lane >= off) x += y;
        }
        if (lane == 31) warp_sums[warp] = x;
        __syncthreads();
        if (warp == 0) {
            int s = warp_sums[lane];
            #pragma unroll
            for (int off = 1; off < 32; off <<= 1) {
                int y = __shfl_up_sync(0xffffffffu, s, off);
                if (lane >= off) s += y;
            }
            warp_sums[lane] = s;
        }
        __syncthreads();
        int warp_off = (warp > 0) ? warp_sums[warp - 1] : 0;
        int incl = x + warp_off + s_carry;
        if (idx < n) rowptr[idx + 1] = incl;
        __syncthreads();
        if (tid == 1023) s_carry = incl;
        __syncthreads();
    }
}

__global__ void scatter_kernel(const int* __restrict__ src, const int* __restrict__ dst,
                               const int* __restrict__ rowptr, int* __restrict__ fill,
                               int* __restrict__ colsrc, int E) {
    for (int e = blockIdx.x * blockDim.x + threadIdx.x; e < E; e += gridDim.x * blockDim.x) {
        int d = dst[e];
        int pos = atomicAdd(&fill[d], 1);
        colsrc[rowptr[d] + pos] = src[e];
    }
}

// ---------------- SGEMM: C[M,Nc] = A[M,K] * B[K,Nc], row-major, fp32 ----------------
// 128x128 block tile, BK=8, 256 threads, 8x8 micro-tile per thread.
__global__ __launch_bounds__(256) void sgemm_kernel(
    const float* __restrict__ A, const float* __restrict__ B, float* __restrict__ C,
    int M, int Nc, int K)
{
    const int BM = 128, BN = 128, BK = 8;
    __shared__ float As[BK][BM];
    __shared__ float Bs[BK][BN];

    int tid = threadIdx.x;
    int tx = tid & 15, ty = tid >> 4;
    int blockRow = blockIdx.y * BM;
    int blockCol = blockIdx.x * BN;

    float acc[8][8];
    #pragma unroll
    for (int i = 0; i < 8; i++)
        #pragma unroll
        for (int j = 0; j < 8; j++) acc[i][j] = 0.f;

    int aRow = tid >> 1;            // 0..127
    int aCol = (tid & 1) * 4;       // 0 or 4
    int bRow = tid >> 5;            // 0..7
    int bCol = (tid & 31) * 4;      // 0..124

    for (int k0 = 0; k0 < K; k0 += BK) {
        float4 av;
        int gRow = blockRow + aRow;
        if (gRow < M) av = *(const float4*)(A + (size_t)gRow * K + k0 + aCol);
        else          av = make_float4(0.f, 0.f, 0.f, 0.f);
        As[aCol + 0][aRow] = av.x;
        As[aCol + 1][aRow] = av.y;
        As[aCol + 2][aRow] = av.z;
        As[aCol + 3][aRow] = av.w;

        float4 bv = *(const float4*)(B + (size_t)(k0 + bRow) * Nc + blockCol + bCol);
        *(float4*)&Bs[bRow][bCol] = bv;
        __syncthreads();

        #pragma unroll
        for (int k = 0; k < BK; k++) {
            float a[8], b[8];
            #pragma unroll
            for (int i = 0; i < 8; i++) a[i] = As[k][ty * 8 + i];
            #pragma unroll
            for (int j = 0; j < 8; j++) b[j] = Bs[k][tx * 8 + j];
            #pragma unroll
            for (int i = 0; i < 8; i++)
                #pragma unroll
                for (int j = 0; j < 8; j++)
                    acc[i][j] += a[i] * b[j];
        }
        __syncthreads();
    }

    #pragma unroll
    for (int i = 0; i < 8; i++) {
        int r = blockRow + ty * 8 + i;
        if (r < M) {
            float* cp = C + (size_t)r * Nc + blockCol + tx * 8;
            *(float4*)(cp)     = make_float4(acc[i][0], acc[i][1], acc[i][2], acc[i][3]);
            *(float4*)(cp + 4) = make_float4(acc[i][4], acc[i][5], acc[i][6], acc[i][7]);
        }
    }
}

// ---------------- el/er: per (node, head) dot with attention vectors ----------------
template <int H, int D>
__global__ void el_er_kernel(const float* __restrict__ ft,
                             const float* __restrict__ attn_l, const float* __restrict__ attn_r,
                             float* __restrict__ el, float* __restrict__ er, int Nn)
{
    int idx = blockIdx.x * blockDim.x + threadIdx.x;
    if (idx >= Nn * H) return;
    int n = idx / H, h = idx - n * H;
    const float* f = ft + (size_t)n * (H * D) + h * D;
    const float* al = attn_l + h * D;
    const float* ar = attn_r + h * D;
    float sl = 0.f, sr = 0.f;
    #pragma unroll 4
    for (int d = 0; d < D; d++) {
        float v = f[d];
        sl += v * al[d];
        sr += v * ar[d];
    }
    el[idx] = sl;
    er[idx] = sr;
}

// ---------------- aggregation: one block per dst node ----------------
__device__ __forceinline__ void atomicMaxFloatShared(float* addr, float val) {
    int* ia = (int*)addr;
    int old = *ia;
    while (__int_as_float(old) < val) {
        int assumed = old;
        old = atomicCAS(ia, assumed, __float_as_int(val));
        if (old == assumed) break;
    }
}

template <int H, int D, bool RELU>
__global__ __launch_bounds__(H * D) void aggregate_kernel(
    const float* __restrict__ ft, const float* __restrict__ el, const float* __restrict__ er,
    const float* __restrict__ bias, float* __restrict__ out)
{
    constexpr int C = H * D;
    constexpr int CHUNK = 32;
    int n = blockIdx.x;
    int tid = threadIdx.x;
    int start = g_rowptr[n];
    int deg = g_rowptr[n + 1] - start;

    __shared__ float s_er[H];
    __shared__ float s_max[H];
    __shared__ float s_denom[H];
    __shared__ float s_w[CHUNK * H];
    __shared__ int   s_src[CHUNK];

    if (tid < H) {
        s_er[tid] = er[(size_t)n * H + tid];
        s_max[tid] = -1e30f;
        s_denom[tid] = 0.f;
    }
    __syncthreads();

    // pass 1: per-head max over incoming edges
    for (int i = tid; i < deg * H; i += C) {
        int ei = i / H, h = i - ei * H;
        int s = g_colsrc[start + ei];
        float e = el[(size_t)s * H + h] + s_er[h];
        e = (e > 0.f) ? e : NEG_SLOPE * e;
        atomicMaxFloatShared(&s_max[h], e);
    }
    __syncthreads();

    const int hc = tid / D;
    float acc = 0.f;

    for (int c0 = 0; c0 < deg; c0 += CHUNK) {
        int cnt = min(CHUNK, deg - c0);
        // compute per-edge softmax numerators for this chunk (once per (edge,head))
        for (int i = tid; i < cnt * H; i += C) {
            int ei = i / H, h = i - ei * H;
            int s = g_colsrc[start + c0 + ei];
            if (h == 0) s_src[ei] = s;
            float e = el[(size_t)s * H + h] + s_er[h];
            e = (e > 0.f) ? e : NEG_SLOPE * e;
            float w = __expf(e - s_max[h]);
            s_w[ei * H + h] = w;
            atomicAdd(&s_denom[h], w);
        }
        __syncthreads();
        // gather + weighted accumulate; unroll x4 for MLP
        int ei = 0;
        for (; ei + 4 <= cnt; ei += 4) {
            int   s0 = s_src[ei + 0], s1 = s_src[ei + 1], s2 = s_src[ei + 2], s3 = s_src[ei + 3];
            float w0 = s_w[(ei + 0) * H + hc], w1 = s_w[(ei + 1) * H + hc];
            float w2 = s_w[(ei + 2) * H + hc], w3 = s_w[(ei + 3) * H + hc];
            float f0 = ft[(size_t)s0 * C + tid];
            float f1 = ft[(size_t)s1 * C + tid];
            float f2 = ft[(size_t)s2 * C + tid];
            float f3 = ft[(size_t)s3 * C + tid];
            acc += w0 * f0; acc += w1 * f1; acc += w2 * f2; acc += w3 * f3;
        }
        for (; ei < cnt; ei++) {
            acc += s_w[ei * H + hc] * ft[(size_t)s_src[ei] * C + tid];
        }
        __syncthreads();
    }

    float o = (deg > 0) ? acc / s_denom[hc] : 0.f;
    o += bias[tid];
    if (RELU) o = fmaxf(o, 0.f);
    out[(size_t)n * C + tid] = o;
}

// ---------------- launch ----------------
extern "C" void kernel_launch(void* const* d_in, const int* in_sizes, int n_in,
                              void* d_out, int out_size)
{
    const float* feat    = (const float*)d_in[0];
    const int*   src     = (const int*)  d_in[1];
    const int*   dst     = (const int*)  d_in[2];
    const float* W1      = (const float*)d_in[3];
    const float* attn_l1 = (const float*)d_in[4];
    const float* attn_r1 = (const float*)d_in[5];
    const float* bias1   = (const float*)d_in[6];
    const float* W2      = (const float*)d_in[7];
    const float* attn_l2 = (const float*)d_in[8];
    const float* attn_r2 = (const float*)d_in[9];
    const float* bias2   = (const float*)d_in[10];
    float* out = (float*)d_out;

    float *ft1, *h1, *el1, *er1, *ft2, *el2, *er2;
    int *cnt, *rowptr, *colsrc;
    cudaGetSymbolAddress((void**)&ft1,    g_ft1);
    cudaGetSymbolAddress((void**)&h1,     g_h1);
    cudaGetSymbolAddress((void**)&el1,    g_el1);
    cudaGetSymbolAddress((void**)&er1,    g_er1);
    cudaGetSymbolAddress((void**)&ft2,    g_ft2);
    cudaGetSymbolAddress((void**)&el2,    g_el2);
    cudaGetSymbolAddress((void**)&er2,    g_er2);
    cudaGetSymbolAddress((void**)&cnt,    g_cnt);
    cudaGetSymbolAddress((void**)&rowptr, g_rowptr);
    cudaGetSymbolAddress((void**)&colsrc, g_colsrc);

    // ---- CSR build (per launch; graph topology is an input) ----
    zero_int_kernel<<<256, 256>>>(cnt, N_NODES);
    count_dst_kernel<<<2048, 256>>>(dst, cnt, N_EDGES);
    scan_kernel<<<1, 1024>>>(cnt, rowptr, N_NODES);
    zero_int_kernel<<<256, 256>>>(cnt, N_NODES);   // reuse as fill cursor
    scatter_kernel<<<2048, 256>>>(src, dst, rowptr, cnt, colsrc, N_EDGES);

    // ---- layer 1: H=4, D=64, C=256, relu ----
    {
        dim3 grid(256 / 128, (N_NODES + 127) / 128);
        sgemm_kernel<<<grid, 256>>>(feat, W1, ft1, N_NODES, 256, 256);
    }
    el_er_kernel<4, 64><<<(N_NODES * 4 + 255) / 256, 256>>>(ft1, attn_l1, attn_r1, el1, er1, N_NODES);
    aggregate_kernel<4, 64, true><<<N_NODES, 256>>>(ft1, el1, er1, bias1, h1);

    // ---- layer 2: H=1, D=128, C=128, no relu ----
    {
        dim3 grid(128 / 128, (N_NODES + 127) / 128);
        sgemm_kernel<<<grid, 256>>>(h1, W2, ft2, N_NODES, 128, 256);
    }
    el_er_kernel<1, 128><<<(N_NODES + 255) / 256, 256>>>(ft2, attn_l2, attn_r2, el2, er2, N_NODES);
    aggregate_kernel<1, 128, false><<<N_NODES, 128>>>(ft2, el2, er2, bias2, out);
}

// round 2
// speedup vs baseline: 1.4378x; 1.4378x over previous
#include <cuda_runtime.h>
#include <math.h>

#define N_NODES 50000
#define N_EDGES 800000
#define NEG_SLOPE 0.2f

// ---------------- scratch (device globals; no allocation allowed) ----------------
__device__ float g_ft1[N_NODES * 256];
__device__ float g_h1 [N_NODES * 256];
__device__ float g_el1[N_NODES * 4];
__device__ float g_er1[N_NODES * 4];
__device__ float g_ft2[N_NODES * 128];
__device__ float g_el2[N_NODES];
__device__ float g_er2[N_NODES];
__device__ int   g_cnt[N_NODES];          // histogram, then reused as fill cursor
__device__ int   g_rowptr[N_NODES + 1];
__device__ int   g_colsrc[N_EDGES];       // src node id per CSR slot
__device__ int   g_eslot[N_EDGES];        // CSR slot of each original edge
__device__ float g_w[N_EDGES * 4];        // per-(slot,head) softmax numerators

// ---------------- small utils ----------------
__global__ void zero_int_kernel(int* __restrict__ p, int n) {
    for (int i = blockIdx.x * blockDim.x + threadIdx.x; i < n; i += gridDim.x * blockDim.x)
        p[i] = 0;
}

__global__ void count_dst_kernel(const int* __restrict__ dst, int* __restrict__ cnt, int E) {
    for (int e = blockIdx.x * blockDim.x + threadIdx.x; e < E; e += gridDim.x * blockDim.x)
        atomicAdd(&cnt[dst[e]], 1);
}

// single-block exclusive scan: rowptr[0]=0; rowptr[i+1]=sum(cnt[0..i])
__global__ void scan_kernel(const int* __restrict__ cnt, int* __restrict__ rowptr, int n) {
    __shared__ int warp_sums[32];
    __shared__ int s_carry;
    int tid = threadIdx.x;
    if (tid == 0) { s_carry = 0; rowptr[0] = 0; }
    __syncthreads();
    for (int base = 0; base < n; base += 1024) {
        int idx = base + tid;
        int v = (idx < n) ? cnt[idx] : 0;
        int lane = tid & 31, warp = tid >> 5;
        int x = v;
        #pragma unroll
        for (int off = 1; off < 32; off <<= 1) {
            int y = __shfl_up_sync(0xffffffffu, x, off);
            if (lane >= off) x += y;
        }
        if (lane == 31) warp_sums[warp] = x;
        __syncthreads();
        if (warp == 0) {
            int s = warp_sums[lane];
            #pragma unroll
            for (int off = 1; off < 32; off <<= 1) {
                int y = __shfl_up_sync(0xffffffffu, s, off);
                if (lane >= off) s += y;
            }
            warp_sums[lane] = s;
        }
        __syncthreads();
        int warp_off = (warp > 0) ? warp_sums[warp - 1] : 0;
        int incl = x + warp_off + s_carry;
        if (idx < n) rowptr[idx + 1] = incl;
        __syncthreads();
        if (tid == 1023) s_carry = incl;
        __syncthreads();
    }
}

__global__ void scatter_kernel(const int* __restrict__ src, const int* __restrict__ dst,
                               const int* __restrict__ rowptr, int* __restrict__ fill,
                               int* __restrict__ colsrc, int* __restrict__ eslot, int E) {
    for (int e = blockIdx.x * blockDim.x + threadIdx.x; e < E; e += gridDim.x * blockDim.x) {
        int d = dst[e];
        int pos = atomicAdd(&fill[d], 1);
        int slot = rowptr[d] + pos;
        colsrc[slot] = src[e];
        eslot[e] = slot;
    }
}

// ---------------- SGEMM: C[M,Nc] = A[M,K] * B[K,Nc], row-major, fp32 ----------------
__global__ __launch_bounds__(256) void sgemm_kernel(
    const float* __restrict__ A, const float* __restrict__ B, float* __restrict__ C,
    int M, int Nc, int K)
{
    const int BM = 128, BN = 128, BK = 8;
    __shared__ float As[BK][BM];
    __shared__ float Bs[BK][BN];

    int tid = threadIdx.x;
    int tx = tid & 15, ty = tid >> 4;
    int blockRow = blockIdx.y * BM;
    int blockCol = blockIdx.x * BN;

    float acc[8][8];
    #pragma unroll
    for (int i = 0; i < 8; i++)
        #pragma unroll
        for (int j = 0; j < 8; j++) acc[i][j] = 0.f;

    int aRow = tid >> 1;
    int aCol = (tid & 1) * 4;
    int bRow = tid >> 5;
    int bCol = (tid & 31) * 4;

    for (int k0 = 0; k0 < K; k0 += BK) {
        float4 av;
        int gRow = blockRow + aRow;
        if (gRow < M) av = *(const float4*)(A + (size_t)gRow * K + k0 + aCol);
        else          av = make_float4(0.f, 0.f, 0.f, 0.f);
        As[aCol + 0][aRow] = av.x;
        As[aCol + 1][aRow] = av.y;
        As[aCol + 2][aRow] = av.z;
        As[aCol + 3][aRow] = av.w;

        float4 bv = *(const float4*)(B + (size_t)(k0 + bRow) * Nc + blockCol + bCol);
        *(float4*)&Bs[bRow][bCol] = bv;
        __syncthreads();

        #pragma unroll
        for (int k = 0; k < BK; k++) {
            float a[8], b[8];
            #pragma unroll
            for (int i = 0; i < 8; i++) a[i] = As[k][ty * 8 + i];
            #pragma unroll
            for (int j = 0; j < 8; j++) b[j] = Bs[k][tx * 8 + j];
            #pragma unroll
            for (int i = 0; i < 8; i++)
                #pragma unroll
                for (int j = 0; j < 8; j++)
                    acc[i][j] += a[i] * b[j];
        }
        __syncthreads();
    }

    #pragma unroll
    for (int i = 0; i < 8; i++) {
        int r = blockRow + ty * 8 + i;
        if (r < M) {
            float* cp = C + (size_t)r * Nc + blockCol + tx * 8;
            *(float4*)(cp)     = make_float4(acc[i][0], acc[i][1], acc[i][2], acc[i][3]);
            *(float4*)(cp + 4) = make_float4(acc[i][4], acc[i][5], acc[i][6], acc[i][7]);
        }
    }
}

// ---------------- el/er: per (node, head) dot with attention vectors ----------------
template <int H, int D>
__global__ void el_er_kernel(const float* __restrict__ ft,
                             const float* __restrict__ attn_l, const float* __restrict__ attn_r,
                             float* __restrict__ el, float* __restrict__ er, int Nn)
{
    int idx = blockIdx.x * blockDim.x + threadIdx.x;
    if (idx >= Nn * H) return;
    int n = idx / H, h = idx - n * H;
    const float4* f  = (const float4*)(ft + (size_t)n * (H * D) + h * D);
    const float4* al = (const float4*)(attn_l + h * D);
    const float4* ar = (const float4*)(attn_r + h * D);
    float sl = 0.f, sr = 0.f;
    #pragma unroll
    for (int d = 0; d < D / 4; d++) {
        float4 v = f[d];
        float4 a = __ldg(&al[d]);
        float4 b = __ldg(&ar[d]);
        sl += v.x * a.x + v.y * a.y + v.z * a.z + v.w * a.w;
        sr += v.x * b.x + v.y * b.y + v.z * b.z + v.w * b.w;
    }
    el[idx] = sl;
    er[idx] = sr;
}

// ---------------- edge-parallel softmax numerators (no max pass: |e| <~ 8) ----------------
__device__ __forceinline__ float leaky_exp(float e) {
    e = (e > 0.f) ? e : NEG_SLOPE * e;
    return __expf(e);
}

__global__ void edge_weight4_kernel(const int* __restrict__ src, const int* __restrict__ dst,
                                    const int* __restrict__ eslot,
                                    const float* __restrict__ el, const float* __restrict__ er,
                                    float* __restrict__ w, int E)
{
    int e = blockIdx.x * blockDim.x + threadIdx.x;
    if (e >= E) return;
    int s = src[e], d = dst[e];
    float4 l = *(const float4*)(el + (size_t)s * 4);
    float4 r = *(const float4*)(er + (size_t)d * 4);
    float4 wv;
    wv.x = leaky_exp(l.x + r.x);
    wv.y = leaky_exp(l.y + r.y);
    wv.z = leaky_exp(l.z + r.z);
    wv.w = leaky_exp(l.w + r.w);
    *(float4*)(w + (size_t)eslot[e] * 4) = wv;
}

__global__ void edge_weight1_kernel(const int* __restrict__ src, const int* __restrict__ dst,
                                    const int* __restrict__ eslot,
                                    const float* __restrict__ el, const float* __restrict__ er,
                                    float* __restrict__ w, int E)
{
    int e = blockIdx.x * blockDim.x + threadIdx.x;
    if (e >= E) return;
    w[eslot[e]] = leaky_exp(el[src[e]] + er[dst[e]]);
}

// ---------------- aggregation: warp per dst node, float4 channels ----------------
// H=4,D=64 (C=256, ITER=2) or H=1,D=128 (C=128, ITER=1)
template <int H, int D, bool RELU>
__global__ __launch_bounds__(256) void aggregate_kernel(
    const float* __restrict__ ft, const float* __restrict__ w,
    const int* __restrict__ rowptr, const int* __restrict__ colsrc,
    const float* __restrict__ bias, float* __restrict__ out, int Nn)
{
    constexpr int C = H * D;
    constexpr int ITER = C / 128;
    int warp = threadIdx.x >> 5, lane = threadIdx.x & 31;
    int n = blockIdx.x * 8 + warp;
    if (n >= Nn) return;
    int start = rowptr[n];
    int deg = rowptr[n + 1] - start;

    float4 acc[ITER];
    float wsum[ITER];
    #pragma unroll
    for (int i = 0; i < ITER; i++) { acc[i] = make_float4(0.f, 0.f, 0.f, 0.f); wsum[i] = 0.f; }

    const bool lo = (lane < 16);   // head selector within each 128-channel iter (H=4)

    int k = 0;
    for (; k + 2 <= deg; k += 2) {
        int j0 = start + k, j1 = j0 + 1;
        int s0 = __ldg(&colsrc[j0]);
        int s1 = __ldg(&colsrc[j1]);
        float wc0[ITER], wc1[ITER];
        if (H == 4) {
            float4 wv0 = __ldg((const float4*)(w + (size_t)j0 * 4));
            float4 wv1 = __ldg((const float4*)(w + (size_t)j1 * 4));
            wc0[0] = lo ? wv0.x : wv0.y;  wc1[0] = lo ? wv1.x : wv1.y;
            if (ITER > 1) { wc0[1] = lo ? wv0.z : wv0.w;  wc1[1] = lo ? wv1.z : wv1.w; }
        } else {
            wc0[0] = __ldg(&w[j0]);
            wc1[0] = __ldg(&w[j1]);
        }
        #pragma unroll
        for (int i = 0; i < ITER; i++) {
            float4 f0 = *(const float4*)(ft + (size_t)s0 * C + i * 128 + lane * 4);
            float4 f1 = *(const float4*)(ft + (size_t)s1 * C + i * 128 + lane * 4);
            acc[i].x += wc0[i] * f0.x + wc1[i] * f1.x;
            acc[i].y += wc0[i] * f0.y + wc1[i] * f1.y;
            acc[i].z += wc0[i] * f0.z + wc1[i] * f1.z;
            acc[i].w += wc0[i] * f0.w + wc1[i] * f1.w;
            wsum[i] += wc0[i] + wc1[i];
        }
    }
    if (k < deg) {
        int j0 = start + k;
        int s0 = __ldg(&colsrc[j0]);
        float wc0[ITER];
        if (H == 4) {
            float4 wv0 = __ldg((const float4*)(w + (size_t)j0 * 4));
            wc0[0] = lo ? wv0.x : wv0.y;
            if (ITER > 1) wc0[1] = lo ? wv0.z : wv0.w;
        } else {
            wc0[0] = __ldg(&w[j0]);
        }
        #pragma unroll
        for (int i = 0; i < ITER; i++) {
            float4 f0 = *(const float4*)(ft + (size_t)s0 * C + i * 128 + lane * 4);
            acc[i].x += wc0[i] * f0.x;
            acc[i].y += wc0[i] * f0.y;
            acc[i].z += wc0[i] * f0.z;
            acc[i].w += wc0[i] * f0.w;
            wsum[i] += wc0[i];
        }
    }

    #pragma unroll
    for (int i = 0; i < ITER; i++) {
        float inv = (deg > 0) ? (1.f / wsum[i]) : 0.f;
        float4 b = __ldg((const float4*)(bias + i * 128 + lane * 4));
        float4 o;
        o.x = acc[i].x * inv + b.x;
        o.y = acc[i].y * inv + b.y;
        o.z = acc[i].z * inv + b.z;
        o.w = acc[i].w * inv + b.w;
        if (RELU) {
            o.x = fmaxf(o.x, 0.f); o.y = fmaxf(o.y, 0.f);
            o.z = fmaxf(o.z, 0.f); o.w = fmaxf(o.w, 0.f);
        }
        *(float4*)(out + (size_t)n * C + i * 128 + lane * 4) = o;
    }
}

// ---------------- launch ----------------
extern "C" void kernel_launch(void* const* d_in, const int* in_sizes, int n_in,
                              void* d_out, int out_size)
{
    const float* feat    = (const float*)d_in[0];
    const int*   src     = (const int*)  d_in[1];
    const int*   dst     = (const int*)  d_in[2];
    const float* W1      = (const float*)d_in[3];
    const float* attn_l1 = (const float*)d_in[4];
    const float* attn_r1 = (const float*)d_in[5];
    const float* bias1   = (const float*)d_in[6];
    const float* W2      = (const float*)d_in[7];
    const float* attn_l2 = (const float*)d_in[8];
    const float* attn_r2 = (const float*)d_in[9];
    const float* bias2   = (const float*)d_in[10];
    float* out = (float*)d_out;

    float *ft1, *h1, *el1, *er1, *ft2, *el2, *er2, *w;
    int *cnt, *rowptr, *colsrc, *eslot;
    cudaGetSymbolAddress((void**)&ft1,    g_ft1);
    cudaGetSymbolAddress((void**)&h1,     g_h1);
    cudaGetSymbolAddress((void**)&el1,    g_el1);
    cudaGetSymbolAddress((void**)&er1,    g_er1);
    cudaGetSymbolAddress((void**)&ft2,    g_ft2);
    cudaGetSymbolAddress((void**)&el2,    g_el2);
    cudaGetSymbolAddress((void**)&er2,    g_er2);
    cudaGetSymbolAddress((void**)&w,      g_w);
    cudaGetSymbolAddress((void**)&cnt,    g_cnt);
    cudaGetSymbolAddress((void**)&rowptr, g_rowptr);
    cudaGetSymbolAddress((void**)&colsrc, g_colsrc);
    cudaGetSymbolAddress((void**)&eslot,  g_eslot);

    // ---- CSR build ----
    zero_int_kernel<<<256, 256>>>(cnt, N_NODES);
    count_dst_kernel<<<2048, 256>>>(dst, cnt, N_EDGES);
    scan_kernel<<<1, 1024>>>(cnt, rowptr, N_NODES);
    zero_int_kernel<<<256, 256>>>(cnt, N_NODES);   // reuse as fill cursor
    scatter_kernel<<<2048, 256>>>(src, dst, rowptr, cnt, colsrc, eslot, N_EDGES);

    // ---- layer 1: H=4, D=64, C=256, relu ----
    {
        dim3 grid(256 / 128, (N_NODES + 127) / 128);
        sgemm_kernel<<<grid, 256>>>(feat, W1, ft1, N_NODES, 256, 256);
    }
    el_er_kernel<4, 64><<<(N_NODES * 4 + 255) / 256, 256>>>(ft1, attn_l1, attn_r1, el1, er1, N_NODES);
    edge_weight4_kernel<<<(N_EDGES + 255) / 256, 256>>>(src, dst, eslot, el1, er1, w, N_EDGES);
    aggregate_kernel<4, 64, true><<<(N_NODES + 7) / 8, 256>>>(ft1, w, rowptr, colsrc, bias1, h1, N_NODES);

    // ---- layer 2: H=1, D=128, C=128, no relu ----
    {
        dim3 grid(128 / 128, (N_NODES + 127) / 128);
        sgemm_kernel<<<grid, 256>>>(h1, W2, ft2, N_NODES, 128, 256);
    }
    el_er_kernel<1, 128><<<(N_NODES + 255) / 256, 256>>>(ft2, attn_l2, attn_r2, el2, er2, N_NODES);
    edge_weight1_kernel<<<(N_EDGES + 255) / 256, 256>>>(src, dst, eslot, el2, er2, w, N_EDGES);
    aggregate_kernel<1, 128, false><<<(N_NODES + 7) / 8, 256>>>(ft2, w, rowptr, colsrc, bias2, out, N_NODES);
}

// round 3
// speedup vs baseline: 1.4960x; 1.0405x over previous
#include <cuda_runtime.h>
#include <math.h>
#include <stdint.h>

#define N_NODES 50000
#define N_EDGES 800000
#define NEG_SLOPE 0.2f

// ---------------- scratch (device globals; no allocation allowed) ----------------
__device__ float g_ft1[N_NODES * 256];
__device__ float g_h1 [N_NODES * 256];
__device__ float g_el1[N_NODES * 4];
__device__ float g_er1[N_NODES * 4];
__device__ float g_ft2[N_NODES * 128];
__device__ float g_el2[N_NODES];
__device__ float g_er2[N_NODES];
__device__ int   g_cnt[N_NODES];          // histogram, then reused as fill cursor
__device__ int   g_rowptr[N_NODES + 1];
__device__ int   g_colsrc[N_EDGES];       // src node id per CSR slot
__device__ int   g_eslot[N_EDGES];        // CSR slot of each original edge
__device__ float g_w[N_EDGES * 4];        // per-(slot,head) softmax numerators

// ---------------- small utils ----------------
__global__ void zero_int_kernel(int* __restrict__ p, int n) {
    for (int i = blockIdx.x * blockDim.x + threadIdx.x; i < n; i += gridDim.x * blockDim.x)
        p[i] = 0;
}

__global__ void count_dst_kernel(const int* __restrict__ dst, int* __restrict__ cnt, int E) {
    for (int e = blockIdx.x * blockDim.x + threadIdx.x; e < E; e += gridDim.x * blockDim.x)
        atomicAdd(&cnt[dst[e]], 1);
}

// single-block exclusive scan: rowptr[0]=0; rowptr[i+1]=sum(cnt[0..i])
__global__ void scan_kernel(const int* __restrict__ cnt, int* __restrict__ rowptr, int n) {
    __shared__ int warp_sums[32];
    __shared__ int s_carry;
    int tid = threadIdx.x;
    if (tid == 0) { s_carry = 0; rowptr[0] = 0; }
    __syncthreads();
    for (int base = 0; base < n; base += 1024) {
        int idx = base + tid;
        int v = (idx < n) ? cnt[idx] : 0;
        int lane = tid & 31, warp = tid >> 5;
        int x = v;
        #pragma unroll
        for (int off = 1; off < 32; off <<= 1) {
            int y = __shfl_up_sync(0xffffffffu, x, off);
            if (lane >= off) x += y;
        }
        if (lane == 31) warp_sums[warp] = x;
        __syncthreads();
        if (warp == 0) {
            int s = warp_sums[lane];
            #pragma unroll
            for (int off = 1; off < 32; off <<= 1) {
                int y = __shfl_up_sync(0xffffffffu, s, off);
                if (lane >= off) s += y;
            }
            warp_sums[lane] = s;
        }
        __syncthreads();
        int warp_off = (warp > 0) ? warp_sums[warp - 1] : 0;
        int incl = x + warp_off + s_carry;
        if (idx < n) rowptr[idx + 1] = incl;
        __syncthreads();
        if (tid == 1023) s_carry = incl;
        __syncthreads();
    }
}

__global__ void scatter_kernel(const int* __restrict__ src, const int* __restrict__ dst,
                               const int* __restrict__ rowptr, int* __restrict__ fill,
                               int* __restrict__ colsrc, int* __restrict__ eslot, int E) {
    for (int e = blockIdx.x * blockDim.x + threadIdx.x; e < E; e += gridDim.x * blockDim.x) {
        int d = dst[e];
        int pos = atomicAdd(&fill[d], 1);
        int slot = rowptr[d] + pos;
        colsrc[slot] = src[e];
        eslot[e] = slot;
    }
}

// ---------------- tf32 split-MMA GEMM: C[M,Nc] = A[M,K] * B[K,Nc] ----------------
// 128x64 block tile, BK=16, 256 threads (8 warps, 4x2), warp tile 32x32.
// Each fp32 operand split into hi+lo tf32; 3 MMAs: Ahi*Bhi + Alo*Bhi + Ahi*Blo.
__device__ __forceinline__ float tf32_round(float x) {
    uint32_t u;
    asm("cvt.rna.tf32.f32 %0, %1;" : "=r"(u) : "f"(x));
    return __uint_as_float(u);
}

#define MMA_TF32(d, a0, a1, a2, a3, b0, b1)                                   \
    asm volatile("mma.sync.aligned.m16n8k8.row.col.f32.tf32.tf32.f32 "        \
                 "{%0,%1,%2,%3}, {%4,%5,%6,%7}, {%8,%9}, {%0,%1,%2,%3};"      \
                 : "+f"(d[0]), "+f"(d[1]), "+f"(d[2]), "+f"(d[3])             \
                 : "r"(a0), "r"(a1), "r"(a2), "r"(a3), "r"(b0), "r"(b1))

__global__ __launch_bounds__(256) void mma_gemm_kernel(
    const float* __restrict__ A, const float* __restrict__ B, float* __restrict__ C,
    int M, int Nc, int K)
{
    const int BM = 128, BN = 64, BK = 16;
    __shared__ float As_hi[BK][132];
    __shared__ float As_lo[BK][132];
    __shared__ float Bs_hi[BK][68];
    __shared__ float Bs_lo[BK][68];

    int tid = threadIdx.x, lane = tid & 31, warp = tid >> 5;
    int wm = warp >> 1, wn = warp & 1;              // 4x2 warp grid
    int blockRow = blockIdx.y * BM;
    int blockCol = blockIdx.x * BN;
    int g = lane >> 2, q = lane & 3;                // group / thread-in-group

    float acc[2][4][4];
    #pragma unroll
    for (int i = 0; i < 2; i++)
        #pragma unroll
        for (int j = 0; j < 4; j++)
            #pragma unroll
            for (int c = 0; c < 4; c++) acc[i][j][c] = 0.f;

    for (int k0 = 0; k0 < K; k0 += BK) {
        // load A tile: 128 rows x 16 cols = 512 float4, 2 per thread
        #pragma unroll
        for (int l = 0; l < 2; l++) {
            int idx = tid + l * 256;
            int r = idx >> 2, cg = (idx & 3) * 4;
            float4 v;
            if (blockRow + r < M) v = *(const float4*)(A + (size_t)(blockRow + r) * K + k0 + cg);
            else                  v = make_float4(0.f, 0.f, 0.f, 0.f);
            float hx = tf32_round(v.x), hy = tf32_round(v.y);
            float hz = tf32_round(v.z), hw = tf32_round(v.w);
            As_hi[cg + 0][r] = hx;  As_lo[cg + 0][r] = tf32_round(v.x - hx);
            As_hi[cg + 1][r] = hy;  As_lo[cg + 1][r] = tf32_round(v.y - hy);
            As_hi[cg + 2][r] = hz;  As_lo[cg + 2][r] = tf32_round(v.z - hz);
            As_hi[cg + 3][r] = hw;  As_lo[cg + 3][r] = tf32_round(v.w - hw);
        }
        // load B tile: 16 rows x 64 cols = 256 float4, 1 per thread
        {
            int r = tid >> 4, cg = (tid & 15) * 4;
            float4 v = *(const float4*)(B + (size_t)(k0 + r) * Nc + blockCol + cg);
            float hx = tf32_round(v.x), hy = tf32_round(v.y);
            float hz = tf32_round(v.z), hw = tf32_round(v.w);
            Bs_hi[r][cg + 0] = hx;  Bs_lo[r][cg + 0] = tf32_round(v.x - hx);
            Bs_hi[r][cg + 1] = hy;  Bs_lo[r][cg + 1] = tf32_round(v.y - hy);
            Bs_hi[r][cg + 2] = hz;  Bs_lo[r][cg + 2] = tf32_round(v.z - hz);
            Bs_hi[r][cg + 3] = hw;  Bs_lo[r][cg + 3] = tf32_round(v.w - hw);
        }
        __syncthreads();

        #pragma unroll
        for (int ks = 0; ks < BK; ks += 8) {
            uint32_t ah[2][4], al[2][4], bh[4][2], bl[4][2];
            #pragma unroll
            for (int i = 0; i < 2; i++) {
                int mb = wm * 32 + i * 16 + g;
                ah[i][0] = __float_as_uint(As_hi[ks + q][mb]);
                ah[i][1] = __float_as_uint(As_hi[ks + q][mb + 8]);
                ah[i][2] = __float_as_uint(As_hi[ks + 4 + q][mb]);
                ah[i][3] = __float_as_uint(As_hi[ks + 4 + q][mb + 8]);
                al[i][0] = __float_as_uint(As_lo[ks + q][mb]);
                al[i][1] = __float_as_uint(As_lo[ks + q][mb + 8]);
                al[i][2] = __float_as_uint(As_lo[ks + 4 + q][mb]);
                al[i][3] = __float_as_uint(As_lo[ks + 4 + q][mb + 8]);
            }
            #pragma unroll
            for (int j = 0; j < 4; j++) {
                int nb = wn * 32 + j * 8 + g;
                bh[j][0] = __float_as_uint(Bs_hi[ks + q][nb]);
                bh[j][1] = __float_as_uint(Bs_hi[ks + 4 + q][nb]);
                bl[j][0] = __float_as_uint(Bs_lo[ks + q][nb]);
                bl[j][1] = __float_as_uint(Bs_lo[ks + 4 + q][nb]);
            }
            #pragma unroll
            for (int i = 0; i < 2; i++)
                #pragma unroll
                for (int j = 0; j < 4; j++) {
                    MMA_TF32(acc[i][j], ah[i][0], ah[i][1], ah[i][2], ah[i][3], bh[j][0], bh[j][1]);
                    MMA_TF32(acc[i][j], al[i][0], al[i][1], al[i][2], al[i][3], bh[j][0], bh[j][1]);
                    MMA_TF32(acc[i][j], ah[i][0], ah[i][1], ah[i][2], ah[i][3], bl[j][0], bl[j][1]);
                }
        }
        __syncthreads();
    }

    // store C
    #pragma unroll
    for (int i = 0; i < 2; i++) {
        int r0 = blockRow + wm * 32 + i * 16 + g;
        int r1 = r0 + 8;
        #pragma unroll
        for (int j = 0; j < 4; j++) {
            int c = blockCol + wn * 32 + j * 8 + q * 2;
            if (r0 < M) *(float2*)(C + (size_t)r0 * Nc + c) = make_float2(acc[i][j][0], acc[i][j][1]);
            if (r1 < M) *(float2*)(C + (size_t)r1 * Nc + c) = make_float2(acc[i][j][2], acc[i][j][3]);
        }
    }
}

// ---------------- el/er: per (node, head) dot with attention vectors ----------------
template <int H, int D>
__global__ void el_er_kernel(const float* __restrict__ ft,
                             const float* __restrict__ attn_l, const float* __restrict__ attn_r,
                             float* __restrict__ el, float* __restrict__ er, int Nn)
{
    int idx = blockIdx.x * blockDim.x + threadIdx.x;
    if (idx >= Nn * H) return;
    int n = idx / H, h = idx - n * H;
    const float4* f  = (const float4*)(ft + (size_t)n * (H * D) + h * D);
    const float4* al = (const float4*)(attn_l + h * D);
    const float4* ar = (const float4*)(attn_r + h * D);
    float sl = 0.f, sr = 0.f;
    #pragma unroll
    for (int d = 0; d < D / 4; d++) {
        float4 v = f[d];
        float4 a = __ldg(&al[d]);
        float4 b = __ldg(&ar[d]);
        sl += v.x * a.x + v.y * a.y + v.z * a.z + v.w * a.w;
        sr += v.x * b.x + v.y * b.y + v.z * b.z + v.w * b.w;
    }
    el[idx] = sl;
    er[idx] = sr;
}

// ---------------- edge-parallel softmax numerators (no max pass: |e| <~ 8) ----------------
__device__ __forceinline__ float leaky_exp(float e) {
    e = (e > 0.f) ? e : NEG_SLOPE * e;
    return __expf(e);
}

__global__ void edge_weight4_kernel(const int* __restrict__ src, const int* __restrict__ dst,
                                    const int* __restrict__ eslot,
                                    const float* __restrict__ el, const float* __restrict__ er,
                                    float* __restrict__ w, int E)
{
    int e = blockIdx.x * blockDim.x + threadIdx.x;
    if (e >= E) return;
    int s = src[e], d = dst[e];
    float4 l = *(const float4*)(el + (size_t)s * 4);
    float4 r = *(const float4*)(er + (size_t)d * 4);
    float4 wv;
    wv.x = leaky_exp(l.x + r.x);
    wv.y = leaky_exp(l.y + r.y);
    wv.z = leaky_exp(l.z + r.z);
    wv.w = leaky_exp(l.w + r.w);
    *(float4*)(w + (size_t)eslot[e] * 4) = wv;
}

__global__ void edge_weight1_kernel(const int* __restrict__ src, const int* __restrict__ dst,
                                    const int* __restrict__ eslot,
                                    const float* __restrict__ el, const float* __restrict__ er,
                                    float* __restrict__ w, int E)
{
    int e = blockIdx.x * blockDim.x + threadIdx.x;
    if (e >= E) return;
    w[eslot[e]] = leaky_exp(el[src[e]] + er[dst[e]]);
}

// ---------------- aggregation: warp per dst node, float4 channels ----------------
template <int H, int D, bool RELU>
__global__ __launch_bounds__(256) void aggregate_kernel(
    const float* __restrict__ ft, const float* __restrict__ w,
    const int* __restrict__ rowptr, const int* __restrict__ colsrc,
    const float* __restrict__ bias, float* __restrict__ out, int Nn)
{
    constexpr int C = H * D;
    constexpr int ITER = C / 128;
    int warp = threadIdx.x >> 5, lane = threadIdx.x & 31;
    int n = blockIdx.x * 8 + warp;
    if (n >= Nn) return;
    int start = rowptr[n];
    int deg = rowptr[n + 1] - start;

    float4 acc[ITER];
    float wsum[ITER];
    #pragma unroll
    for (int i = 0; i < ITER; i++) { acc[i] = make_float4(0.f, 0.f, 0.f, 0.f); wsum[i] = 0.f; }

    const bool lo = (lane < 16);

    int k = 0;
    for (; k + 2 <= deg; k += 2) {
        int j0 = start + k, j1 = j0 + 1;
        int s0 = __ldg(&colsrc[j0]);
        int s1 = __ldg(&colsrc[j1]);
        float wc0[ITER], wc1[ITER];
        if (H == 4) {
            float4 wv0 = __ldg((const float4*)(w + (size_t)j0 * 4));
            float4 wv1 = __ldg((const float4*)(w + (size_t)j1 * 4));
            wc0[0] = lo ? wv0.x : wv0.y;  wc1[0] = lo ? wv1.x : wv1.y;
            if (ITER > 1) { wc0[1] = lo ? wv0.z : wv0.w;  wc1[1] = lo ? wv1.z : wv1.w; }
        } else {
            wc0[0] = __ldg(&w[j0]);
            wc1[0] = __ldg(&w[j1]);
        }
        #pragma unroll
        for (int i = 0; i < ITER; i++) {
            float4 f0 = *(const float4*)(ft + (size_t)s0 * C + i * 128 + lane * 4);
            float4 f1 = *(const float4*)(ft + (size_t)s1 * C + i * 128 + lane * 4);
            acc[i].x += wc0[i] * f0.x + wc1[i] * f1.x;
            acc[i].y += wc0[i] * f0.y + wc1[i] * f1.y;
            acc[i].z += wc0[i] * f0.z + wc1[i] * f1.z;
            acc[i].w += wc0[i] * f0.w + wc1[i] * f1.w;
            wsum[i] += wc0[i] + wc1[i];
        }
    }
    if (k < deg) {
        int j0 = start + k;
        int s0 = __ldg(&colsrc[j0]);
        float wc0[ITER];
        if (H == 4) {
            float4 wv0 = __ldg((const float4*)(w + (size_t)j0 * 4));
            wc0[0] = lo ? wv0.x : wv0.y;
            if (ITER > 1) wc0[1] = lo ? wv0.z : wv0.w;
        } else {
            wc0[0] = __ldg(&w[j0]);
        }
        #pragma unroll
        for (int i = 0; i < ITER; i++) {
            float4 f0 = *(const float4*)(ft + (size_t)s0 * C + i * 128 + lane * 4);
            acc[i].x += wc0[i] * f0.x;
            acc[i].y += wc0[i] * f0.y;
            acc[i].z += wc0[i] * f0.z;
            acc[i].w += wc0[i] * f0.w;
            wsum[i] += wc0[i];
        }
    }

    #pragma unroll
    for (int i = 0; i < ITER; i++) {
        float inv = (deg > 0) ? (1.f / wsum[i]) : 0.f;
        float4 b = __ldg((const float4*)(bias + i * 128 + lane * 4));
        float4 o;
        o.x = acc[i].x * inv + b.x;
        o.y = acc[i].y * inv + b.y;
        o.z = acc[i].z * inv + b.z;
        o.w = acc[i].w * inv + b.w;
        if (RELU) {
            o.x = fmaxf(o.x, 0.f); o.y = fmaxf(o.y, 0.f);
            o.z = fmaxf(o.z, 0.f); o.w = fmaxf(o.w, 0.f);
        }
        *(float4*)(out + (size_t)n * C + i * 128 + lane * 4) = o;
    }
}

// ---------------- launch ----------------
extern "C" void kernel_launch(void* const* d_in, const int* in_sizes, int n_in,
                              void* d_out, int out_size)
{
    const float* feat    = (const float*)d_in[0];
    const int*   src     = (const int*)  d_in[1];
    const int*   dst     = (const int*)  d_in[2];
    const float* W1      = (const float*)d_in[3];
    const float* attn_l1 = (const float*)d_in[4];
    const float* attn_r1 = (const float*)d_in[5];
    const float* bias1   = (const float*)d_in[6];
    const float* W2      = (const float*)d_in[7];
    const float* attn_l2 = (const float*)d_in[8];
    const float* attn_r2 = (const float*)d_in[9];
    const float* bias2   = (const float*)d_in[10];
    float* out = (float*)d_out;

    float *ft1, *h1, *el1, *er1, *ft2, *el2, *er2, *w;
    int *cnt, *rowptr, *colsrc, *eslot;
    cudaGetSymbolAddress((void**)&ft1,    g_ft1);
    cudaGetSymbolAddress((void**)&h1,     g_h1);
    cudaGetSymbolAddress((void**)&el1,    g_el1);
    cudaGetSymbolAddress((void**)&er1,    g_er1);
    cudaGetSymbolAddress((void**)&ft2,    g_ft2);
    cudaGetSymbolAddress((void**)&el2,    g_el2);
    cudaGetSymbolAddress((void**)&er2,    g_er2);
    cudaGetSymbolAddress((void**)&w,      g_w);
    cudaGetSymbolAddress((void**)&cnt,    g_cnt);
    cudaGetSymbolAddress((void**)&rowptr, g_rowptr);
    cudaGetSymbolAddress((void**)&colsrc, g_colsrc);
    cudaGetSymbolAddress((void**)&eslot,  g_eslot);

    // ---- CSR build ----
    zero_int_kernel<<<256, 256>>>(cnt, N_NODES);
    count_dst_kernel<<<2048, 256>>>(dst, cnt, N_EDGES);
    scan_kernel<<<1, 1024>>>(cnt, rowptr, N_NODES);
    zero_int_kernel<<<256, 256>>>(cnt, N_NODES);   // reuse as fill cursor
    scatter_kernel<<<2048, 256>>>(src, dst, rowptr, cnt, colsrc, eslot, N_EDGES);

    // ---- layer 1: H=4, D=64, C=256, relu ----
    {
        dim3 grid(256 / 64, (N_NODES + 127) / 128);
        mma_gemm_kernel<<<grid, 256>>>(feat, W1, ft1, N_NODES, 256, 256);
    }
    el_er_kernel<4, 64><<<(N_NODES * 4 + 255) / 256, 256>>>(ft1, attn_l1, attn_r1, el1, er1, N_NODES);
    edge_weight4_kernel<<<(N_EDGES + 255) / 256, 256>>>(src, dst, eslot, el1, er1, w, N_EDGES);
    aggregate_kernel<4, 64, true><<<(N_NODES + 7) / 8, 256>>>(ft1, w, rowptr, colsrc, bias1, h1, N_NODES);

    // ---- layer 2: H=1, D=128, C=128, no relu ----
    {
        dim3 grid(128 / 64, (N_NODES + 127) / 128);
        mma_gemm_kernel<<<grid, 256>>>(h1, W2, ft2, N_NODES, 128, 256);
    }
    el_er_kernel<1, 128><<<(N_NODES + 255) / 256, 256>>>(ft2, attn_l2, attn_r2, el2, er2, N_NODES);
    edge_weight1_kernel<<<(N_EDGES + 255) / 256, 256>>>(src, dst, eslot, el2, er2, w, N_EDGES);
    aggregate_kernel<1, 128, false><<<(N_NODES + 7) / 8, 256>>>(ft2, w, rowptr, colsrc, bias2, out, N_NODES);
}

// round 4
// speedup vs baseline: 1.8277x; 1.2217x over previous
#include <cuda_runtime.h>
#include <math.h>
#include <stdint.h>

#define N_NODES 50000
#define N_EDGES 800000
#define NEG_SLOPE 0.2f

// ---------------- scratch (device globals; no allocation allowed) ----------------
__device__ float g_ft1[N_NODES * 256];
__device__ float g_h1 [N_NODES * 256];
__device__ float g_el1[N_NODES * 4];
__device__ float g_er1[N_NODES * 4];
__device__ float g_ft2[N_NODES * 128];
__device__ float g_el2[N_NODES];
__device__ float g_er2[N_NODES];
__device__ int   g_cnt[N_NODES];          // degree histogram, consumed by scatter
__device__ int   g_rowptr[N_NODES + 1];
__device__ int   g_colsrc[N_EDGES];       // src node id per CSR slot

// ---------------- small utils ----------------
__global__ void zero_int_kernel(int* __restrict__ p, int n) {
    for (int i = blockIdx.x * blockDim.x + threadIdx.x; i < n; i += gridDim.x * blockDim.x)
        p[i] = 0;
}

__global__ void count_dst_kernel(const int* __restrict__ dst, int* __restrict__ cnt, int E) {
    for (int e = blockIdx.x * blockDim.x + threadIdx.x; e < E; e += gridDim.x * blockDim.x)
        atomicAdd(&cnt[dst[e]], 1);
}

// single-block exclusive scan: rowptr[0]=0; rowptr[i+1]=sum(cnt[0..i])
__global__ void scan_kernel(const int* __restrict__ cnt, int* __restrict__ rowptr, int n) {
    __shared__ int warp_sums[32];
    __shared__ int s_carry;
    int tid = threadIdx.x;
    if (tid == 0) { s_carry = 0; rowptr[0] = 0; }
    __syncthreads();
    for (int base = 0; base < n; base += 1024) {
        int idx = base + tid;
        int v = (idx < n) ? cnt[idx] : 0;
        int lane = tid & 31, warp = tid >> 5;
        int x = v;
        #pragma unroll
        for (int off = 1; off < 32; off <<= 1) {
            int y = __shfl_up_sync(0xffffffffu, x, off);
            if (lane >= off) x += y;
        }
        if (lane == 31) warp_sums[warp] = x;
        __syncthreads();
        if (warp == 0) {
            int s = warp_sums[lane];
            #pragma unroll
            for (int off = 1; off < 32; off <<= 1) {
                int y = __shfl_up_sync(0xffffffffu, s, off);
                if (lane >= off) s += y;
            }
            warp_sums[lane] = s;
        }
        __syncthreads();
        int warp_off = (warp > 0) ? warp_sums[warp - 1] : 0;
        int incl = x + warp_off + s_carry;
        if (idx < n) rowptr[idx + 1] = incl;
        __syncthreads();
        if (tid == 1023) s_carry = incl;
        __syncthreads();
    }
}

// consumes cnt (degree histogram) via atomicSub — no second zero pass needed
__global__ void scatter_kernel(const int* __restrict__ src, const int* __restrict__ dst,
                               const int* __restrict__ rowptr, int* __restrict__ cnt,
                               int* __restrict__ colsrc, int E) {
    for (int e = blockIdx.x * blockDim.x + threadIdx.x; e < E; e += gridDim.x * blockDim.x) {
        int d = dst[e];
        int pos = atomicSub(&cnt[d], 1);          // returns old count in [1..deg]
        colsrc[rowptr[d] + pos - 1] = src[e];
    }
}

// ---------------- tf32 split-MMA GEMM: C[M,Nc] = A[M,K] * B[K,Nc] ----------------
// 128x64 block tile, BK=32, 256 threads (8 warps, 4x2), warp tile 32x32.
// fp32 split into hi+lo tf32; 3 MMAs: Ahi*Bhi + Alo*Bhi + Ahi*Blo (rel_err ~1e-6).
// A smem [m][k] stride 36 (vector STS.128, conflict-free LDS); B [k][n] stride 72.
__device__ __forceinline__ float tf32_round(float x) {
    uint32_t u;
    asm("cvt.rna.tf32.f32 %0, %1;" : "=r"(u) : "f"(x));
    return __uint_as_float(u);
}

#define MMA_TF32(d, a0, a1, a2, a3, b0, b1)                                   \
    asm volatile("mma.sync.aligned.m16n8k8.row.col.f32.tf32.tf32.f32 "        \
                 "{%0,%1,%2,%3}, {%4,%5,%6,%7}, {%8,%9}, {%0,%1,%2,%3};"      \
                 : "+f"(d[0]), "+f"(d[1]), "+f"(d[2]), "+f"(d[3])             \
                 : "r"(a0), "r"(a1), "r"(a2), "r"(a3), "r"(b0), "r"(b1))

__global__ __launch_bounds__(256) void mma_gemm_kernel(
    const float* __restrict__ A, const float* __restrict__ B, float* __restrict__ C,
    int M, int Nc, int K)
{
    const int BM = 128, BN = 64, BK = 32;
    const int ASTR = 36, BSTR = 72;
    __shared__ float As_hi[BM][ASTR];
    __shared__ float As_lo[BM][ASTR];
    __shared__ float Bs_hi[BK][BSTR];
    __shared__ float Bs_lo[BK][BSTR];

    int tid = threadIdx.x, lane = tid & 31, warp = tid >> 5;
    int wm = warp >> 1, wn = warp & 1;              // 4x2 warp grid
    int blockRow = blockIdx.y * BM;
    int blockCol = blockIdx.x * BN;
    int g = lane >> 2, q = lane & 3;

    float acc[2][4][4];
    #pragma unroll
    for (int i = 0; i < 2; i++)
        #pragma unroll
        for (int j = 0; j < 4; j++)
            #pragma unroll
            for (int c = 0; c < 4; c++) acc[i][j][c] = 0.f;

    for (int k0 = 0; k0 < K; k0 += BK) {
        // A tile: 128 x 32 floats = 1024 float4, 4 per thread
        #pragma unroll
        for (int l = 0; l < 4; l++) {
            int idx = tid + l * 256;
            int r = idx >> 3, cg = (idx & 7) * 4;
            float4 v;
            if (blockRow + r < M) v = *(const float4*)(A + (size_t)(blockRow + r) * K + k0 + cg);
            else                  v = make_float4(0.f, 0.f, 0.f, 0.f);
            float4 h, o;
            h.x = tf32_round(v.x); o.x = tf32_round(v.x - h.x);
            h.y = tf32_round(v.y); o.y = tf32_round(v.y - h.y);
            h.z = tf32_round(v.z); o.z = tf32_round(v.z - h.z);
            h.w = tf32_round(v.w); o.w = tf32_round(v.w - h.w);
            *(float4*)&As_hi[r][cg] = h;
            *(float4*)&As_lo[r][cg] = o;
        }
        // B tile: 32 x 64 floats = 512 float4, 2 per thread
        #pragma unroll
        for (int l = 0; l < 2; l++) {
            int idx = tid + l * 256;
            int r = idx >> 4, cg = (idx & 15) * 4;
            float4 v = *(const float4*)(B + (size_t)(k0 + r) * Nc + blockCol + cg);
            float4 h, o;
            h.x = tf32_round(v.x); o.x = tf32_round(v.x - h.x);
            h.y = tf32_round(v.y); o.y = tf32_round(v.y - h.y);
            h.z = tf32_round(v.z); o.z = tf32_round(v.z - h.z);
            h.w = tf32_round(v.w); o.w = tf32_round(v.w - h.w);
            *(float4*)&Bs_hi[r][cg] = h;
            *(float4*)&Bs_lo[r][cg] = o;
        }
        __syncthreads();

        #pragma unroll
        for (int ks = 0; ks < BK; ks += 8) {
            uint32_t ah[2][4], al[2][4], bh[4][2], bl[4][2];
            #pragma unroll
            for (int i = 0; i < 2; i++) {
                int mb = wm * 32 + i * 16 + g;
                ah[i][0] = __float_as_uint(As_hi[mb    ][ks + q]);
                ah[i][1] = __float_as_uint(As_hi[mb + 8][ks + q]);
                ah[i][2] = __float_as_uint(As_hi[mb    ][ks + q + 4]);
                ah[i][3] = __float_as_uint(As_hi[mb + 8][ks + q + 4]);
                al[i][0] = __float_as_uint(As_lo[mb    ][ks + q]);
                al[i][1] = __float_as_uint(As_lo[mb + 8][ks + q]);
                al[i][2] = __float_as_uint(As_lo[mb    ][ks + q + 4]);
                al[i][3] = __float_as_uint(As_lo[mb + 8][ks + q + 4]);
            }
            #pragma unroll
            for (int j = 0; j < 4; j++) {
                int nb = wn * 32 + j * 8 + g;
                bh[j][0] = __float_as_uint(Bs_hi[ks + q    ][nb]);
                bh[j][1] = __float_as_uint(Bs_hi[ks + q + 4][nb]);
                bl[j][0] = __float_as_uint(Bs_lo[ks + q    ][nb]);
                bl[j][1] = __float_as_uint(Bs_lo[ks + q + 4][nb]);
            }
            #pragma unroll
            for (int i = 0; i < 2; i++)
                #pragma unroll
                for (int j = 0; j < 4; j++) {
                    MMA_TF32(acc[i][j], ah[i][0], ah[i][1], ah[i][2], ah[i][3], bh[j][0], bh[j][1]);
                    MMA_TF32(acc[i][j], al[i][0], al[i][1], al[i][2], al[i][3], bh[j][0], bh[j][1]);
                    MMA_TF32(acc[i][j], ah[i][0], ah[i][1], ah[i][2], ah[i][3], bl[j][0], bl[j][1]);
                }
        }
        __syncthreads();
    }

    #pragma unroll
    for (int i = 0; i < 2; i++) {
        int r0 = blockRow + wm * 32 + i * 16 + g;
        int r1 = r0 + 8;
        #pragma unroll
        for (int j = 0; j < 4; j++) {
            int c = blockCol + wn * 32 + j * 8 + q * 2;
            if (r0 < M) *(float2*)(C + (size_t)r0 * Nc + c) = make_float2(acc[i][j][0], acc[i][j][1]);
            if (r1 < M) *(float2*)(C + (size_t)r1 * Nc + c) = make_float2(acc[i][j][2], acc[i][j][3]);
        }
    }
}

// ---------------- el/er: per (node, head) dot with attention vectors ----------------
template <int H, int D>
__global__ void el_er_kernel(const float* __restrict__ ft,
                             const float* __restrict__ attn_l, const float* __restrict__ attn_r,
                             float* __restrict__ el, float* __restrict__ er, int Nn)
{
    int idx = blockIdx.x * blockDim.x + threadIdx.x;
    if (idx >= Nn * H) return;
    int n = idx / H, h = idx - n * H;
    const float4* f  = (const float4*)(ft + (size_t)n * (H * D) + h * D);
    const float4* al = (const float4*)(attn_l + h * D);
    const float4* ar = (const float4*)(attn_r + h * D);
    float sl = 0.f, sr = 0.f;
    #pragma unroll
    for (int d = 0; d < D / 4; d++) {
        float4 v = f[d];
        float4 a = __ldg(&al[d]);
        float4 b = __ldg(&ar[d]);
        sl += v.x * a.x + v.y * a.y + v.z * a.z + v.w * a.w;
        sr += v.x * b.x + v.y * b.y + v.z * b.z + v.w * b.w;
    }
    el[idx] = sl;
    er[idx] = sr;
}

// ---------------- fused softmax + aggregation (no max pass: |e| small) ----------------
__device__ __forceinline__ float leaky_exp(float e) {
    e = (e > 0.f) ? e : NEG_SLOPE * e;
    return __expf(e);
}

// layer 1: H=4, D=64, C=256. 2 warps per node; each warp owns 128 channels
// (part 0 -> heads 0/1, part 1 -> heads 2/3). RELU output.
__global__ __launch_bounds__(256) void aggregate1_kernel(
    const float* __restrict__ ft, const float* __restrict__ el, const float* __restrict__ er,
    const int* __restrict__ rowptr, const int* __restrict__ colsrc,
    const float* __restrict__ bias, float* __restrict__ out, int Nn)
{
    int warp = threadIdx.x >> 5, lane = threadIdx.x & 31;
    int n = blockIdx.x * 4 + (warp >> 1);
    int part = warp & 1;
    if (n >= Nn) return;
    int start = rowptr[n];
    int deg = rowptr[n + 1] - start;

    const bool hlo = (lane < 16);   // first head of this part
    float4 er4 = __ldg((const float4*)(er + (size_t)n * 4));
    float er_h = part ? (hlo ? er4.z : er4.w) : (hlo ? er4.x : er4.y);

    float4 acc = make_float4(0.f, 0.f, 0.f, 0.f);
    float wsum = 0.f;
    const float* ftp = ft + part * 128 + lane * 4;

    int k = 0;
    for (; k + 4 <= deg; k += 4) {
        int s0 = __ldg(&colsrc[start + k + 0]);
        int s1 = __ldg(&colsrc[start + k + 1]);
        int s2 = __ldg(&colsrc[start + k + 2]);
        int s3 = __ldg(&colsrc[start + k + 3]);
        float4 l0 = __ldg((const float4*)(el + (size_t)s0 * 4));
        float4 l1 = __ldg((const float4*)(el + (size_t)s1 * 4));
        float4 l2 = __ldg((const float4*)(el + (size_t)s2 * 4));
        float4 l3 = __ldg((const float4*)(el + (size_t)s3 * 4));
        float4 f0 = *(const float4*)(ftp + (size_t)s0 * 256);
        float4 f1 = *(const float4*)(ftp + (size_t)s1 * 256);
        float4 f2 = *(const float4*)(ftp + (size_t)s2 * 256);
        float4 f3 = *(const float4*)(ftp + (size_t)s3 * 256);
        float w0 = leaky_exp((part ? (hlo ? l0.z : l0.w) : (hlo ? l0.x : l0.y)) + er_h);
        float w1 = leaky_exp((part ? (hlo ? l1.z : l1.w) : (hlo ? l1.x : l1.y)) + er_h);
        float w2 = leaky_exp((part ? (hlo ? l2.z : l2.w) : (hlo ? l2.x : l2.y)) + er_h);
        float w3 = leaky_exp((part ? (hlo ? l3.z : l3.w) : (hlo ? l3.x : l3.y)) + er_h);
        acc.x += w0 * f0.x + w1 * f1.x + w2 * f2.x + w3 * f3.x;
        acc.y += w0 * f0.y + w1 * f1.y + w2 * f2.y + w3 * f3.y;
        acc.z += w0 * f0.z + w1 * f1.z + w2 * f2.z + w3 * f3.z;
        acc.w += w0 * f0.w + w1 * f1.w + w2 * f2.w + w3 * f3.w;
        wsum += (w0 + w1) + (w2 + w3);
    }
    for (; k < deg; k++) {
        int s0 = __ldg(&colsrc[start + k]);
        float4 l0 = __ldg((const float4*)(el + (size_t)s0 * 4));
        float4 f0 = *(const float4*)(ftp + (size_t)s0 * 256);
        float w0 = leaky_exp((part ? (hlo ? l0.z : l0.w) : (hlo ? l0.x : l0.y)) + er_h);
        acc.x += w0 * f0.x; acc.y += w0 * f0.y;
        acc.z += w0 * f0.z; acc.w += w0 * f0.w;
        wsum += w0;
    }

    float inv = (deg > 0) ? (1.f / wsum) : 0.f;
    float4 b = __ldg((const float4*)(bias + part * 128 + lane * 4));
    float4 o;
    o.x = fmaxf(acc.x * inv + b.x, 0.f);
    o.y = fmaxf(acc.y * inv + b.y, 0.f);
    o.z = fmaxf(acc.z * inv + b.z, 0.f);
    o.w = fmaxf(acc.w * inv + b.w, 0.f);
    *(float4*)(out + (size_t)n * 256 + part * 128 + lane * 4) = o;
}

// layer 2: H=1, D=128, C=128. warp per node, no relu (writes final output).
__global__ __launch_bounds__(256) void aggregate2_kernel(
    const float* __restrict__ ft, const float* __restrict__ el, const float* __restrict__ er,
    const int* __restrict__ rowptr, const int* __restrict__ colsrc,
    const float* __restrict__ bias, float* __restrict__ out, int Nn)
{
    int warp = threadIdx.x >> 5, lane = threadIdx.x & 31;
    int n = blockIdx.x * 8 + warp;
    if (n >= Nn) return;
    int start = rowptr[n];
    int deg = rowptr[n + 1] - start;

    float er_n = __ldg(&er[n]);
    float4 acc = make_float4(0.f, 0.f, 0.f, 0.f);
    float wsum = 0.f;
    const float* ftp = ft + lane * 4;

    int k = 0;
    for (; k + 4 <= deg; k += 4) {
        int s0 = __ldg(&colsrc[start + k + 0]);
        int s1 = __ldg(&colsrc[start + k + 1]);
        int s2 = __ldg(&colsrc[start + k + 2]);
        int s3 = __ldg(&colsrc[start + k + 3]);
        float e0 = __ldg(&el[s0]), e1 = __ldg(&el[s1]);
        float e2 = __ldg(&el[s2]), e3 = __ldg(&el[s3]);
        float4 f0 = *(const float4*)(ftp + (size_t)s0 * 128);
        float4 f1 = *(const float4*)(ftp + (size_t)s1 * 128);
        float4 f2 = *(const float4*)(ftp + (size_t)s2 * 128);
        float4 f3 = *(const float4*)(ftp + (size_t)s3 * 128);
        float w0 = leaky_exp(e0 + er_n), w1 = leaky_exp(e1 + er_n);
        float w2 = leaky_exp(e2 + er_n), w3 = leaky_exp(e3 + er_n);
        acc.x += w0 * f0.x + w1 * f1.x + w2 * f2.x + w3 * f3.x;
        acc.y += w0 * f0.y + w1 * f1.y + w2 * f2.y + w3 * f3.y;
        acc.z += w0 * f0.z + w1 * f1.z + w2 * f2.z + w3 * f3.z;
        acc.w += w0 * f0.w + w1 * f1.w + w2 * f2.w + w3 * f3.w;
        wsum += (w0 + w1) + (w2 + w3);
    }
    for (; k < deg; k++) {
        int s0 = __ldg(&colsrc[start + k]);
        float w0 = leaky_exp(__ldg(&el[s0]) + er_n);
        float4 f0 = *(const float4*)(ftp + (size_t)s0 * 128);
        acc.x += w0 * f0.x; acc.y += w0 * f0.y;
        acc.z += w0 * f0.z; acc.w += w0 * f0.w;
        wsum += w0;
    }

    float inv = (deg > 0) ? (1.f / wsum) : 0.f;
    float4 b = __ldg((const float4*)(bias + lane * 4));
    float4 o;
    o.x = acc.x * inv + b.x;
    o.y = acc.y * inv + b.y;
    o.z = acc.z * inv + b.z;
    o.w = acc.w * inv + b.w;
    *(float4*)(out + (size_t)n * 128 + lane * 4) = o;
}

// ---------------- launch ----------------
extern "C" void kernel_launch(void* const* d_in, const int* in_sizes, int n_in,
                              void* d_out, int out_size)
{
    const float* feat    = (const float*)d_in[0];
    const int*   src     = (const int*)  d_in[1];
    const int*   dst     = (const int*)  d_in[2];
    const float* W1      = (const float*)d_in[3];
    const float* attn_l1 = (const float*)d_in[4];
    const float* attn_r1 = (const float*)d_in[5];
    const float* bias1   = (const float*)d_in[6];
    const float* W2      = (const float*)d_in[7];
    const float* attn_l2 = (const float*)d_in[8];
    const float* attn_r2 = (const float*)d_in[9];
    const float* bias2   = (const float*)d_in[10];
    float* out = (float*)d_out;

    float *ft1, *h1, *el1, *er1, *ft2, *el2, *er2;
    int *cnt, *rowptr, *colsrc;
    cudaGetSymbolAddress((void**)&ft1,    g_ft1);
    cudaGetSymbolAddress((void**)&h1,     g_h1);
    cudaGetSymbolAddress((void**)&el1,    g_el1);
    cudaGetSymbolAddress((void**)&er1,    g_er1);
    cudaGetSymbolAddress((void**)&ft2,    g_ft2);
    cudaGetSymbolAddress((void**)&el2,    g_el2);
    cudaGetSymbolAddress((void**)&er2,    g_er2);
    cudaGetSymbolAddress((void**)&cnt,    g_cnt);
    cudaGetSymbolAddress((void**)&rowptr, g_rowptr);
    cudaGetSymbolAddress((void**)&colsrc, g_colsrc);

    // ---- CSR build (4 launches) ----
    zero_int_kernel<<<256, 256>>>(cnt, N_NODES);
    count_dst_kernel<<<2048, 256>>>(dst, cnt, N_EDGES);
    scan_kernel<<<1, 1024>>>(cnt, rowptr, N_NODES);
    scatter_kernel<<<2048, 256>>>(src, dst, rowptr, cnt, colsrc, N_EDGES);

    // ---- layer 1: H=4, D=64, C=256, relu ----
    {
        dim3 grid(256 / 64, (N_NODES + 127) / 128);
        mma_gemm_kernel<<<grid, 256>>>(feat, W1, ft1, N_NODES, 256, 256);
    }
    el_er_kernel<4, 64><<<(N_NODES * 4 + 255) / 256, 256>>>(ft1, attn_l1, attn_r1, el1, er1, N_NODES);
    aggregate1_kernel<<<(N_NODES + 3) / 4, 256>>>(ft1, el1, er1, rowptr, colsrc, bias1, h1, N_NODES);

    // ---- layer 2: H=1, D=128, C=128, no relu ----
    {
        dim3 grid(128 / 64, (N_NODES + 127) / 128);
        mma_gemm_kernel<<<grid, 256>>>(h1, W2, ft2, N_NODES, 128, 256);
    }
    el_er_kernel<1, 128><<<(N_NODES + 255) / 256, 256>>>(ft2, attn_l2, attn_r2, el2, er2, N_NODES);
    aggregate2_kernel<<<(N_NODES + 7) / 8, 256>>>(ft2, el2, er2, rowptr, colsrc, bias2, out, N_NODES);
}

// round 5
// speedup vs baseline: 2.0139x; 1.1019x over previous
#include <cuda_runtime.h>
#include <math.h>
#include <stdint.h>

#define N_NODES 50000
#define N_EDGES 800000
#define NEG_SLOPE 0.2f

// ---------------- scratch (device globals; no allocation allowed) ----------------
__device__ float g_ft1[N_NODES * 256];
__device__ float g_h1 [N_NODES * 256];
__device__ float g_el1[N_NODES * 4];
__device__ float g_er1[N_NODES * 4];
__device__ float g_ft2[N_NODES * 128];
__device__ float g_el2[N_NODES];
__device__ float g_er2[N_NODES];
__device__ int   g_cnt[N_NODES];
__device__ int   g_rowptr[N_NODES + 1];
__device__ int   g_colsrc[N_EDGES];

// ---------------- small utils ----------------
__global__ void zero_int_kernel(int* __restrict__ p, int n) {
    for (int i = blockIdx.x * blockDim.x + threadIdx.x; i < n; i += gridDim.x * blockDim.x)
        p[i] = 0;
}

__global__ void zero2_float_kernel(float* __restrict__ a, float* __restrict__ b, int n) {
    for (int i = blockIdx.x * blockDim.x + threadIdx.x; i < n; i += gridDim.x * blockDim.x) {
        a[i] = 0.f;
        b[i] = 0.f;
    }
}

__global__ void count_dst_kernel(const int* __restrict__ dst, int* __restrict__ cnt, int E) {
    for (int e = blockIdx.x * blockDim.x + threadIdx.x; e < E; e += gridDim.x * blockDim.x)
        atomicAdd(&cnt[dst[e]], 1);
}

// single-block exclusive scan: rowptr[0]=0; rowptr[i+1]=sum(cnt[0..i])
__global__ void scan_kernel(const int* __restrict__ cnt, int* __restrict__ rowptr, int n) {
    __shared__ int warp_sums[32];
    __shared__ int s_carry;
    int tid = threadIdx.x;
    if (tid == 0) { s_carry = 0; rowptr[0] = 0; }
    __syncthreads();
    for (int base = 0; base < n; base += 1024) {
        int idx = base + tid;
        int v = (idx < n) ? cnt[idx] : 0;
        int lane = tid & 31, warp = tid >> 5;
        int x = v;
        #pragma unroll
        for (int off = 1; off < 32; off <<= 1) {
            int y = __shfl_up_sync(0xffffffffu, x, off);
            if (lane >= off) x += y;
        }
        if (lane == 31) warp_sums[warp] = x;
        __syncthreads();
        if (warp == 0) {
            int s = warp_sums[lane];
            #pragma unroll
            for (int off = 1; off < 32; off <<= 1) {
                int y = __shfl_up_sync(0xffffffffu, s, off);
                if (lane >= off) s += y;
            }
            warp_sums[lane] = s;
        }
        __syncthreads();
        int warp_off = (warp > 0) ? warp_sums[warp - 1] : 0;
        int incl = x + warp_off + s_carry;
        if (idx < n) rowptr[idx + 1] = incl;
        __syncthreads();
        if (tid == 1023) s_carry = incl;
        __syncthreads();
    }
}

// consumes cnt (degree histogram) via atomicSub — no second zero pass needed
__global__ void scatter_kernel(const int* __restrict__ src, const int* __restrict__ dst,
                               const int* __restrict__ rowptr, int* __restrict__ cnt,
                               int* __restrict__ colsrc, int E) {
    for (int e = blockIdx.x * blockDim.x + threadIdx.x; e < E; e += gridDim.x * blockDim.x) {
        int d = dst[e];
        int pos = atomicSub(&cnt[d], 1);
        colsrc[rowptr[d] + pos - 1] = src[e];
    }
}

// ---------------- tf32 split-MMA GEMM + fused el/er epilogue ----------------
// C[M,Nc] = A[M,K]*B[K,Nc]; el/er[r] = dot(C[r, head-cols], attn) computed in-epilogue.
// HEADS==4: BN=64 == D, head = blockIdx.x, direct store. HEADS==1: D=128 spans 2
// col-blocks -> atomicAdd partials (el/er pre-zeroed).
__device__ __forceinline__ float tf32_round(float x) {
    uint32_t u;
    asm("cvt.rna.tf32.f32 %0, %1;" : "=r"(u) : "f"(x));
    return __uint_as_float(u);
}

#define MMA_TF32(d, a0, a1, a2, a3, b0, b1)                                   \
    asm volatile("mma.sync.aligned.m16n8k8.row.col.f32.tf32.tf32.f32 "        \
                 "{%0,%1,%2,%3}, {%4,%5,%6,%7}, {%8,%9}, {%0,%1,%2,%3};"      \
                 : "+f"(d[0]), "+f"(d[1]), "+f"(d[2]), "+f"(d[3])             \
                 : "r"(a0), "r"(a1), "r"(a2), "r"(a3), "r"(b0), "r"(b1))

template <int HEADS>
__global__ __launch_bounds__(256) void mma_gemm_eler_kernel(
    const float* __restrict__ A, const float* __restrict__ B, float* __restrict__ C,
    const float* __restrict__ attn_l, const float* __restrict__ attn_r,
    float* __restrict__ el, float* __restrict__ er,
    int M, int Nc, int K)
{
    const int BM = 128, BN = 64, BK = 32;
    const int ASTR = 36, BSTR = 72;
    __shared__ float As_hi[BM][ASTR];
    __shared__ float As_lo[BM][ASTR];
    __shared__ float Bs_hi[BK][BSTR];
    __shared__ float Bs_lo[BK][BSTR];
    __shared__ float s_el[BM];
    __shared__ float s_er[BM];

    int tid = threadIdx.x, lane = tid & 31, warp = tid >> 5;
    int wm = warp >> 1, wn = warp & 1;
    int blockRow = blockIdx.y * BM;
    int blockCol = blockIdx.x * BN;
    int g = lane >> 2, q = lane & 3;

    float acc[2][4][4];
    #pragma unroll
    for (int i = 0; i < 2; i++)
        #pragma unroll
        for (int j = 0; j < 4; j++)
            #pragma unroll
            for (int c = 0; c < 4; c++) acc[i][j][c] = 0.f;

    for (int k0 = 0; k0 < K; k0 += BK) {
        #pragma unroll
        for (int l = 0; l < 4; l++) {
            int idx = tid + l * 256;
            int r = idx >> 3, cg = (idx & 7) * 4;
            float4 v;
            if (blockRow + r < M) v = *(const float4*)(A + (size_t)(blockRow + r) * K + k0 + cg);
            else                  v = make_float4(0.f, 0.f, 0.f, 0.f);
            float4 h, o;
            h.x = tf32_round(v.x); o.x = tf32_round(v.x - h.x);
            h.y = tf32_round(v.y); o.y = tf32_round(v.y - h.y);
            h.z = tf32_round(v.z); o.z = tf32_round(v.z - h.z);
            h.w = tf32_round(v.w); o.w = tf32_round(v.w - h.w);
            *(float4*)&As_hi[r][cg] = h;
            *(float4*)&As_lo[r][cg] = o;
        }
        #pragma unroll
        for (int l = 0; l < 2; l++) {
            int idx = tid + l * 256;
            int r = idx >> 4, cg = (idx & 15) * 4;
            float4 v = *(const float4*)(B + (size_t)(k0 + r) * Nc + blockCol + cg);
            float4 h, o;
            h.x = tf32_round(v.x); o.x = tf32_round(v.x - h.x);
            h.y = tf32_round(v.y); o.y = tf32_round(v.y - h.y);
            h.z = tf32_round(v.z); o.z = tf32_round(v.z - h.z);
            h.w = tf32_round(v.w); o.w = tf32_round(v.w - h.w);
            *(float4*)&Bs_hi[r][cg] = h;
            *(float4*)&Bs_lo[r][cg] = o;
        }
        __syncthreads();

        #pragma unroll
        for (int ks = 0; ks < BK; ks += 8) {
            uint32_t ah[2][4], al_[2][4], bh[4][2], bl[4][2];
            #pragma unroll
            for (int i = 0; i < 2; i++) {
                int mb = wm * 32 + i * 16 + g;
                ah[i][0] = __float_as_uint(As_hi[mb    ][ks + q]);
                ah[i][1] = __float_as_uint(As_hi[mb + 8][ks + q]);
                ah[i][2] = __float_as_uint(As_hi[mb    ][ks + q + 4]);
                ah[i][3] = __float_as_uint(As_hi[mb + 8][ks + q + 4]);
                al_[i][0] = __float_as_uint(As_lo[mb    ][ks + q]);
                al_[i][1] = __float_as_uint(As_lo[mb + 8][ks + q]);
                al_[i][2] = __float_as_uint(As_lo[mb    ][ks + q + 4]);
                al_[i][3] = __float_as_uint(As_lo[mb + 8][ks + q + 4]);
            }
            #pragma unroll
            for (int j = 0; j < 4; j++) {
                int nb = wn * 32 + j * 8 + g;
                bh[j][0] = __float_as_uint(Bs_hi[ks + q    ][nb]);
                bh[j][1] = __float_as_uint(Bs_hi[ks + q + 4][nb]);
                bl[j][0] = __float_as_uint(Bs_lo[ks + q    ][nb]);
                bl[j][1] = __float_as_uint(Bs_lo[ks + q + 4][nb]);
            }
            #pragma unroll
            for (int i = 0; i < 2; i++)
                #pragma unroll
                for (int j = 0; j < 4; j++) {
                    MMA_TF32(acc[i][j], ah[i][0], ah[i][1], ah[i][2], ah[i][3], bh[j][0], bh[j][1]);
                    MMA_TF32(acc[i][j], al_[i][0], al_[i][1], al_[i][2], al_[i][3], bh[j][0], bh[j][1]);
                    MMA_TF32(acc[i][j], ah[i][0], ah[i][1], ah[i][2], ah[i][3], bl[j][0], bl[j][1]);
                }
        }
        __syncthreads();
    }

    // store C
    #pragma unroll
    for (int i = 0; i < 2; i++) {
        int r0 = blockRow + wm * 32 + i * 16 + g;
        int r1 = r0 + 8;
        #pragma unroll
        for (int j = 0; j < 4; j++) {
            int c = blockCol + wn * 32 + j * 8 + q * 2;
            if (r0 < M) *(float2*)(C + (size_t)r0 * Nc + c) = make_float2(acc[i][j][0], acc[i][j][1]);
            if (r1 < M) *(float2*)(C + (size_t)r1 * Nc + c) = make_float2(acc[i][j][2], acc[i][j][3]);
        }
    }

    // ---- fused el/er epilogue ----
    // partial dots over this thread's 8 columns, for its 4 rows [i][h8]
    float pl[2][2] = {{0.f, 0.f}, {0.f, 0.f}};
    float pr[2][2] = {{0.f, 0.f}, {0.f, 0.f}};
    #pragma unroll
    for (int j = 0; j < 4; j++) {
        int idx = blockCol + wn * 32 + j * 8 + q * 2;   // attn layout [H][D] flattens to col index
        float a0 = __ldg(&attn_l[idx]), a1 = __ldg(&attn_l[idx + 1]);
        float b0 = __ldg(&attn_r[idx]), b1 = __ldg(&attn_r[idx + 1]);
        #pragma unroll
        for (int i = 0; i < 2; i++) {
            pl[i][0] += acc[i][j][0] * a0 + acc[i][j][1] * a1;
            pl[i][1] += acc[i][j][2] * a0 + acc[i][j][3] * a1;
            pr[i][0] += acc[i][j][0] * b0 + acc[i][j][1] * b1;
            pr[i][1] += acc[i][j][2] * b0 + acc[i][j][3] * b1;
        }
    }
    #pragma unroll
    for (int off = 1; off <= 2; off <<= 1) {
        #pragma unroll
        for (int i = 0; i < 2; i++) {
            pl[i][0] += __shfl_xor_sync(0xffffffffu, pl[i][0], off);
            pl[i][1] += __shfl_xor_sync(0xffffffffu, pl[i][1], off);
            pr[i][0] += __shfl_xor_sync(0xffffffffu, pr[i][0], off);
            pr[i][1] += __shfl_xor_sync(0xffffffffu, pr[i][1], off);
        }
    }
    if (wn == 0 && q == 0) {
        #pragma unroll
        for (int i = 0; i < 2; i++) {
            int row = wm * 32 + i * 16 + g;
            s_el[row]     = pl[i][0];  s_el[row + 8] = pl[i][1];
            s_er[row]     = pr[i][0];  s_er[row + 8] = pr[i][1];
        }
    }
    __syncthreads();
    if (wn == 1 && q == 0) {
        #pragma unroll
        for (int i = 0; i < 2; i++) {
            #pragma unroll
            for (int h8 = 0; h8 < 2; h8++) {
                int row = wm * 32 + i * 16 + g + h8 * 8;
                int r = blockRow + row;
                if (r < M) {
                    float vl = pl[i][h8] + s_el[row];
                    float vr = pr[i][h8] + s_er[row];
                    if (HEADS == 1) {
                        atomicAdd(&el[r], vl);
                        atomicAdd(&er[r], vr);
                    } else {
                        el[(size_t)r * HEADS + blockIdx.x] = vl;
                        er[(size_t)r * HEADS + blockIdx.x] = vr;
                    }
                }
            }
        }
    }
}

// ---------------- fused softmax + aggregation ----------------
__device__ __forceinline__ float leaky_exp(float e) {
    e = (e > 0.f) ? e : NEG_SLOPE * e;
    return __expf(e);
}

// layer 1: H=4, D=64, C=256. One warp per node; lane owns 8 channels
// (segment A: c=lane*4 -> heads 0/1; segment B: c=128+lane*4 -> heads 2/3).
__global__ __launch_bounds__(256) void aggregate1_kernel(
    const float* __restrict__ ft, const float* __restrict__ el, const float* __restrict__ er,
    const int* __restrict__ rowptr, const int* __restrict__ colsrc,
    const float* __restrict__ bias, float* __restrict__ out, int Nn)
{
    int warp = threadIdx.x >> 5, lane = threadIdx.x & 31;
    int n = blockIdx.x * 8 + warp;
    if (n >= Nn) return;
    int start = rowptr[n];
    int deg = rowptr[n + 1] - start;

    const bool hlo = (lane < 16);
    float4 er4 = __ldg((const float4*)(er + (size_t)n * 4));
    float erA = hlo ? er4.x : er4.y;
    float erB = hlo ? er4.z : er4.w;

    float4 accA = make_float4(0.f, 0.f, 0.f, 0.f);
    float4 accB = make_float4(0.f, 0.f, 0.f, 0.f);
    float wsumA = 0.f, wsumB = 0.f;
    const float* ftA = ft + lane * 4;
    const float* ftB = ft + 128 + lane * 4;

    int k = 0;
    for (; k + 4 <= deg; k += 4) {
        int s0 = __ldg(&colsrc[start + k + 0]);
        int s1 = __ldg(&colsrc[start + k + 1]);
        int s2 = __ldg(&colsrc[start + k + 2]);
        int s3 = __ldg(&colsrc[start + k + 3]);
        float4 l0 = __ldg((const float4*)(el + (size_t)s0 * 4));
        float4 l1 = __ldg((const float4*)(el + (size_t)s1 * 4));
        float4 l2 = __ldg((const float4*)(el + (size_t)s2 * 4));
        float4 l3 = __ldg((const float4*)(el + (size_t)s3 * 4));
        float4 fA0 = *(const float4*)(ftA + (size_t)s0 * 256);
        float4 fB0 = *(const float4*)(ftB + (size_t)s0 * 256);
        float4 fA1 = *(const float4*)(ftA + (size_t)s1 * 256);
        float4 fB1 = *(const float4*)(ftB + (size_t)s1 * 256);
        float4 fA2 = *(const float4*)(ftA + (size_t)s2 * 256);
        float4 fB2 = *(const float4*)(ftB + (size_t)s2 * 256);
        float4 fA3 = *(const float4*)(ftA + (size_t)s3 * 256);
        float4 fB3 = *(const float4*)(ftB + (size_t)s3 * 256);
        float wA0 = leaky_exp((hlo ? l0.x : l0.y) + erA);
        float wB0 = leaky_exp((hlo ? l0.z : l0.w) + erB);
        float wA1 = leaky_exp((hlo ? l1.x : l1.y) + erA);
        float wB1 = leaky_exp((hlo ? l1.z : l1.w) + erB);
        float wA2 = leaky_exp((hlo ? l2.x : l2.y) + erA);
        float wB2 = leaky_exp((hlo ? l2.z : l2.w) + erB);
        float wA3 = leaky_exp((hlo ? l3.x : l3.y) + erA);
        float wB3 = leaky_exp((hlo ? l3.z : l3.w) + erB);
        accA.x += wA0 * fA0.x + wA1 * fA1.x + wA2 * fA2.x + wA3 * fA3.x;
        accA.y += wA0 * fA0.y + wA1 * fA1.y + wA2 * fA2.y + wA3 * fA3.y;
        accA.z += wA0 * fA0.z + wA1 * fA1.z + wA2 * fA2.z + wA3 * fA3.z;
        accA.w += wA0 * fA0.w + wA1 * fA1.w + wA2 * fA2.w + wA3 * fA3.w;
        accB.x += wB0 * fB0.x + wB1 * fB1.x + wB2 * fB2.x + wB3 * fB3.x;
        accB.y += wB0 * fB0.y + wB1 * fB1.y + wB2 * fB2.y + wB3 * fB3.y;
        accB.z += wB0 * fB0.z + wB1 * fB1.z + wB2 * fB2.z + wB3 * fB3.z;
        accB.w += wB0 * fB0.w + wB1 * fB1.w + wB2 * fB2.w + wB3 * fB3.w;
        wsumA += (wA0 + wA1) + (wA2 + wA3);
        wsumB += (wB0 + wB1) + (wB2 + wB3);
    }
    for (; k < deg; k++) {
        int s0 = __ldg(&colsrc[start + k]);
        float4 l0 = __ldg((const float4*)(el + (size_t)s0 * 4));
        float4 fA0 = *(const float4*)(ftA + (size_t)s0 * 256);
        float4 fB0 = *(const float4*)(ftB + (size_t)s0 * 256);
        float wA0 = leaky_exp((hlo ? l0.x : l0.y) + erA);
        float wB0 = leaky_exp((hlo ? l0.z : l0.w) + erB);
        accA.x += wA0 * fA0.x; accA.y += wA0 * fA0.y;
        accA.z += wA0 * fA0.z; accA.w += wA0 * fA0.w;
        accB.x += wB0 * fB0.x; accB.y += wB0 * fB0.y;
        accB.z += wB0 * fB0.z; accB.w += wB0 * fB0.w;
        wsumA += wA0; wsumB += wB0;
    }

    float invA = (deg > 0) ? (1.f / wsumA) : 0.f;
    float invB = (deg > 0) ? (1.f / wsumB) : 0.f;
    float4 bA = __ldg((const float4*)(bias + lane * 4));
    float4 bB = __ldg((const float4*)(bias + 128 + lane * 4));
    float4 oA, oB;
    oA.x = fmaxf(accA.x * invA + bA.x, 0.f);
    oA.y = fmaxf(accA.y * invA + bA.y, 0.f);
    oA.z = fmaxf(accA.z * invA + bA.z, 0.f);
    oA.w = fmaxf(accA.w * invA + bA.w, 0.f);
    oB.x = fmaxf(accB.x * invB + bB.x, 0.f);
    oB.y = fmaxf(accB.y * invB + bB.y, 0.f);
    oB.z = fmaxf(accB.z * invB + bB.z, 0.f);
    oB.w = fmaxf(accB.w * invB + bB.w, 0.f);
    *(float4*)(out + (size_t)n * 256 + lane * 4) = oA;
    *(float4*)(out + (size_t)n * 256 + 128 + lane * 4) = oB;
}

// layer 2: H=1, D=128. One warp per node, unroll 8, no relu (final output).
__global__ __launch_bounds__(256) void aggregate2_kernel(
    const float* __restrict__ ft, const float* __restrict__ el, const float* __restrict__ er,
    const int* __restrict__ rowptr, const int* __restrict__ colsrc,
    const float* __restrict__ bias, float* __restrict__ out, int Nn)
{
    int warp = threadIdx.x >> 5, lane = threadIdx.x & 31;
    int n = blockIdx.x * 8 + warp;
    if (n >= Nn) return;
    int start = rowptr[n];
    int deg = rowptr[n + 1] - start;

    float er_n = __ldg(&er[n]);
    float4 acc = make_float4(0.f, 0.f, 0.f, 0.f);
    float wsum = 0.f;
    const float* ftp = ft + lane * 4;

    int k = 0;
    for (; k + 8 <= deg; k += 8) {
        int s[8];
        #pragma unroll
        for (int u = 0; u < 8; u++) s[u] = __ldg(&colsrc[start + k + u]);
        float e[8];
        #pragma unroll
        for (int u = 0; u < 8; u++) e[u] = __ldg(&el[s[u]]);
        float4 f[8];
        #pragma unroll
        for (int u = 0; u < 8; u++) f[u] = *(const float4*)(ftp + (size_t)s[u] * 128);
        #pragma unroll
        for (int u = 0; u < 8; u++) {
            float w = leaky_exp(e[u] + er_n);
            acc.x += w * f[u].x; acc.y += w * f[u].y;
            acc.z += w * f[u].z; acc.w += w * f[u].w;
            wsum += w;
        }
    }
    for (; k < deg; k++) {
        int s0 = __ldg(&colsrc[start + k]);
        float w = leaky_exp(__ldg(&el[s0]) + er_n);
        float4 f0 = *(const float4*)(ftp + (size_t)s0 * 128);
        acc.x += w * f0.x; acc.y += w * f0.y;
        acc.z += w * f0.z; acc.w += w * f0.w;
        wsum += w;
    }

    float inv = (deg > 0) ? (1.f / wsum) : 0.f;
    float4 b = __ldg((const float4*)(bias + lane * 4));
    float4 o;
    o.x = acc.x * inv + b.x;
    o.y = acc.y * inv + b.y;
    o.z = acc.z * inv + b.z;
    o.w = acc.w * inv + b.w;
    *(float4*)(out + (size_t)n * 128 + lane * 4) = o;
}

// ---------------- launch ----------------
extern "C" void kernel_launch(void* const* d_in, const int* in_sizes, int n_in,
                              void* d_out, int out_size)
{
    const float* feat    = (const float*)d_in[0];
    const int*   src     = (const int*)  d_in[1];
    const int*   dst     = (const int*)  d_in[2];
    const float* W1      = (const float*)d_in[3];
    const float* attn_l1 = (const float*)d_in[4];
    const float* attn_r1 = (const float*)d_in[5];
    const float* bias1   = (const float*)d_in[6];
    const float* W2      = (const float*)d_in[7];
    const float* attn_l2 = (const float*)d_in[8];
    const float* attn_r2 = (const float*)d_in[9];
    const float* bias2   = (const float*)d_in[10];
    float* out = (float*)d_out;

    float *ft1, *h1, *el1, *er1, *ft2, *el2, *er2;
    int *cnt, *rowptr, *colsrc;
    cudaGetSymbolAddress((void**)&ft1,    g_ft1);
    cudaGetSymbolAddress((void**)&h1,     g_h1);
    cudaGetSymbolAddress((void**)&el1,    g_el1);
    cudaGetSymbolAddress((void**)&er1,    g_er1);
    cudaGetSymbolAddress((void**)&ft2,    g_ft2);
    cudaGetSymbolAddress((void**)&el2,    g_el2);
    cudaGetSymbolAddress((void**)&er2,    g_er2);
    cudaGetSymbolAddress((void**)&cnt,    g_cnt);
    cudaGetSymbolAddress((void**)&rowptr, g_rowptr);
    cudaGetSymbolAddress((void**)&colsrc, g_colsrc);

    // ---- CSR build ----
    zero_int_kernel<<<256, 256>>>(cnt, N_NODES);
    count_dst_kernel<<<2048, 256>>>(dst, cnt, N_EDGES);
    scan_kernel<<<1, 1024>>>(cnt, rowptr, N_NODES);
    scatter_kernel<<<2048, 256>>>(src, dst, rowptr, cnt, colsrc, N_EDGES);

    // ---- layer 1: H=4, D=64, C=256, relu ----
    {
        dim3 grid(256 / 64, (N_NODES + 127) / 128);
        mma_gemm_eler_kernel<4><<<grid, 256>>>(feat, W1, ft1, attn_l1, attn_r1,
                                               el1, er1, N_NODES, 256, 256);
    }
    aggregate1_kernel<<<(N_NODES + 7) / 8, 256>>>(ft1, el1, er1, rowptr, colsrc, bias1, h1, N_NODES);

    // ---- layer 2: H=1, D=128, C=128, no relu ----
    zero2_float_kernel<<<256, 256>>>(el2, er2, N_NODES);
    {
        dim3 grid(128 / 64, (N_NODES + 127) / 128);
        mma_gemm_eler_kernel<1><<<grid, 256>>>(h1, W2, ft2, attn_l2, attn_r2,
                                               el2, er2, N_NODES, 128, 256);
    }
    aggregate2_kernel<<<(N_NODES + 7) / 8, 256>>>(ft2, el2, er2, rowptr, colsrc, bias2, out, N_NODES);
}

// round 7
// speedup vs baseline: 2.0980x; 1.0418x over previous
#include <cuda_runtime.h>
#include <math.h>
#include <stdint.h>

#define N_NODES 50000
#define N_EDGES 800000
#define NEG_SLOPE 0.2f

// ---------------- scratch (device globals; no allocation allowed) ----------------
__device__ float g_ft1[N_NODES * 256];
__device__ float g_h1 [N_NODES * 256];
__device__ float g_el1[N_NODES * 4];
__device__ float g_er1[N_NODES * 4];
__device__ float g_ft2[N_NODES * 128];
__device__ float g_el2p[2 * N_NODES];
__device__ float g_er2p[2 * N_NODES];
__device__ int   g_cnt[N_NODES];
__device__ int   g_rowptr[N_NODES + 1];
__device__ int   g_colsrc[N_EDGES];
__device__ float g_wt1h[256 * 256];   // W1^T hi  [n][k]
__device__ float g_wt1l[256 * 256];   // W1^T lo
__device__ float g_wt2h[128 * 256];   // W2^T hi
__device__ float g_wt2l[128 * 256];   // W2^T lo

// ---------------- helpers ----------------
__device__ __forceinline__ uint32_t smem_u32(const void* p) {
    uint32_t a;
    asm("{ .reg .u64 t; cvta.to.shared.u64 t, %1; cvt.u32.u64 %0, t; }" : "=r"(a) : "l"(p));
    return a;
}
__device__ __forceinline__ float tf32_round(float x) {
    uint32_t u;
    asm("cvt.rna.tf32.f32 %0, %1;" : "=r"(u) : "f"(x));
    return __uint_as_float(u);
}

#define CP_ASYNC16(sa, gp) \
    asm volatile("cp.async.cg.shared.global [%0], [%1], 16;" :: "r"(sa), "l"(gp) : "memory")
#define CP_ASYNC16_Z(sa, gp, sz) \
    asm volatile("cp.async.cg.shared.global [%0], [%1], 16, %2;" :: "r"(sa), "l"(gp), "r"(sz) : "memory")
#define CP_COMMIT()  asm volatile("cp.async.commit_group;" ::: "memory")
#define CP_WAIT(n)   asm volatile("cp.async.wait_group %0;" :: "n"(n) : "memory")

#define MMA_TF32(d, a0, a1, a2, a3, b0, b1)                                   \
    asm volatile("mma.sync.aligned.m16n8k8.row.col.f32.tf32.tf32.f32 "        \
                 "{%0,%1,%2,%3}, {%4,%5,%6,%7}, {%8,%9}, {%0,%1,%2,%3};"      \
                 : "+f"(d[0]), "+f"(d[1]), "+f"(d[2]), "+f"(d[3])             \
                 : "r"(a0), "r"(a1), "r"(a2), "r"(a3), "r"(b0), "r"(b1))

// ---------------- small utils ----------------
__global__ void zero_int_kernel(int* __restrict__ p, int n) {
    for (int i = blockIdx.x * blockDim.x + threadIdx.x; i < n; i += gridDim.x * blockDim.x)
        p[i] = 0;
}

__global__ void count_dst_kernel(const int* __restrict__ dst, int* __restrict__ cnt, int E) {
    for (int e = blockIdx.x * blockDim.x + threadIdx.x; e < E; e += gridDim.x * blockDim.x)
        atomicAdd(&cnt[dst[e]], 1);
}

// transpose + hi/lo tf32 split of both weight matrices
__global__ void transpose_split_kernel(const float* __restrict__ W1, const float* __restrict__ W2,
                                       float* __restrict__ t1h, float* __restrict__ t1l,
                                       float* __restrict__ t2h, float* __restrict__ t2l) {
    int t = blockIdx.x * blockDim.x + threadIdx.x;
    if (t < 65536) {
        int k = t & 255, n = t >> 8;
        float v = W1[k * 256 + n];
        float h = tf32_round(v);
        t1h[n * 256 + k] = h;
        t1l[n * 256 + k] = tf32_round(v - h);
    } else if (t < 98304) {
        int u = t - 65536;
        int k = u & 255, n = u >> 8;
        float v = W2[k * 128 + n];
        float h = tf32_round(v);
        t2h[n * 256 + k] = h;
        t2l[n * 256 + k] = tf32_round(v - h);
    }
}

// single-block exclusive scan
__global__ void scan_kernel(const int* __restrict__ cnt, int* __restrict__ rowptr, int n) {
    __shared__ int warp_sums[32];
    __shared__ int s_carry;
    int tid = threadIdx.x;
    if (tid == 0) { s_carry = 0; rowptr[0] = 0; }
    __syncthreads();
    for (int base = 0; base < n; base += 1024) {
        int idx = base + tid;
        int v = (idx < n) ? cnt[idx] : 0;
        int lane = tid & 31, warp = tid >> 5;
        int x = v;
        #pragma unroll
        for (int off = 1; off < 32; off <<= 1) {
            int y = __shfl_up_sync(0xffffffffu, x, off);
            if (lane >= off) x += y;
        }
        if (lane == 31) warp_sums[warp] = x;
        __syncthreads();
        if (warp == 0) {
            int s = warp_sums[lane];
            #pragma unroll
            for (int off = 1; off < 32; off <<= 1) {
                int y = __shfl_up_sync(0xffffffffu, s, off);
                if (lane >= off) s += y;
            }
            warp_sums[lane] = s;
        }
        __syncthreads();
        int warp_off = (warp > 0) ? warp_sums[warp - 1] : 0;
        int incl = x + warp_off + s_carry;
        if (idx < n) rowptr[idx + 1] = incl;
        __syncthreads();
        if (tid == 1023) s_carry = incl;
        __syncthreads();
    }
}

__global__ void scatter_kernel(const int* __restrict__ src, const int* __restrict__ dst,
                               const int* __restrict__ rowptr, int* __restrict__ cnt,
                               int* __restrict__ colsrc, int E) {
    for (int e = blockIdx.x * blockDim.x + threadIdx.x; e < E; e += gridDim.x * blockDim.x) {
        int d = dst[e];
        int pos = atomicSub(&cnt[d], 1);
        colsrc[rowptr[d] + pos - 1] = src[e];
    }
}

// ---------------- cp.async double-buffered tf32 split GEMM + fused el/er ----------------
// C[M,Nc] = A[M,256] * W; W supplied pre-transposed+split (Bth/Btl [Nc][256]).
// 128x64 tile, BK=32, 2-stage cp.async pipeline. A raw in smem, split at fragment
// load (hi + lo tf32); 3 MMAs per (i,j): hi*hi + lo*hi + hi*lo.
// Smem stride 36 for both operands -> conflict-free fragment LDS.
template <int HEADS>
__global__ __launch_bounds__(256) void mma_gemm_db_kernel(
    const float* __restrict__ A,
    const float* __restrict__ Bth, const float* __restrict__ Btl,
    float* __restrict__ C,
    const float* __restrict__ attn_l, const float* __restrict__ attn_r,
    float* __restrict__ el, float* __restrict__ er,
    int M, int Nc)
{
    const int BM = 128, BN = 64, BK = 32, K = 256;
    const int ASTR = 36, BSTR = 36;
    extern __shared__ float sm[];
    float* As   = sm;                       // [2][BM][ASTR] raw fp32
    float* Bh   = As + 2 * BM * ASTR;       // [2][BN][BSTR] hi
    float* Bl   = Bh + 2 * BN * BSTR;       // [2][BN][BSTR] lo
    float* s_el = Bl + 2 * BN * BSTR;       // [BM]
    float* s_er = s_el + BM;                // [BM]

    uint32_t as_b = smem_u32(As);
    uint32_t bh_b = smem_u32(Bh);
    uint32_t bl_b = smem_u32(Bl);

    int tid = threadIdx.x, lane = tid & 31, warp = tid >> 5;
    int wm = warp >> 1, wn = warp & 1;
    int blockRow = blockIdx.y * BM;
    int blockCol = blockIdx.x * BN;
    int g = lane >> 2, q = lane & 3;

    float acc[2][4][4];
    #pragma unroll
    for (int i = 0; i < 2; i++)
        #pragma unroll
        for (int j = 0; j < 4; j++)
            #pragma unroll
            for (int c = 0; c < 4; c++) acc[i][j][c] = 0.f;

    // ---- async tile loader: one commit group per tile ----
    auto load_tile = [&](int t) {
        int buf = t & 1, k0 = t * BK;
        #pragma unroll
        for (int l = 0; l < 4; l++) {
            int c = tid + l * 256;
            int r = c >> 3, kq = (c & 7) * 4;
            const float* gp = A + (size_t)(blockRow + r) * K + k0 + kq;
            uint32_t sa = as_b + (uint32_t)(((buf * BM + r) * ASTR + kq) * 4);
            uint32_t sz = (blockRow + r < M) ? 16u : 0u;
            CP_ASYNC16_Z(sa, gp, sz);
        }
        #pragma unroll
        for (int l = 0; l < 2; l++) {
            int c = tid + l * 256;
            int n = c >> 3, kq = (c & 7) * 4;
            size_t go = (size_t)(blockCol + n) * K + k0 + kq;
            uint32_t so = (uint32_t)(((buf * BN + n) * BSTR + kq) * 4);
            CP_ASYNC16(bh_b + so, Bth + go);
            CP_ASYNC16(bl_b + so, Btl + go);
        }
        CP_COMMIT();
    };

    load_tile(0);

    #pragma unroll 1
    for (int t = 0; t < K / BK; t++) {
        if (t < K / BK - 1) {
            load_tile(t + 1);
            CP_WAIT(1);
        } else {
            CP_WAIT(0);
        }
        __syncthreads();

        int buf = t & 1;
        const float* Ab  = As + buf * BM * ASTR;
        const float* Bhb = Bh + buf * BN * BSTR;
        const float* Blb = Bl + buf * BN * BSTR;

        #pragma unroll
        for (int ks = 0; ks < BK; ks += 8) {
            uint32_t ah[2][4], al[2][4];
            #pragma unroll
            for (int i = 0; i < 2; i++) {
                int mb = wm * 32 + i * 16 + g;
                float r0 = Ab[(mb    ) * ASTR + ks + q];
                float r1 = Ab[(mb + 8) * ASTR + ks + q];
                float r2 = Ab[(mb    ) * ASTR + ks + q + 4];
                float r3 = Ab[(mb + 8) * ASTR + ks + q + 4];
                float h0 = tf32_round(r0), h1 = tf32_round(r1);
                float h2 = tf32_round(r2), h3 = tf32_round(r3);
                ah[i][0] = __float_as_uint(h0); al[i][0] = __float_as_uint(tf32_round(r0 - h0));
                ah[i][1] = __float_as_uint(h1); al[i][1] = __float_as_uint(tf32_round(r1 - h1));
                ah[i][2] = __float_as_uint(h2); al[i][2] = __float_as_uint(tf32_round(r2 - h2));
                ah[i][3] = __float_as_uint(h3); al[i][3] = __float_as_uint(tf32_round(r3 - h3));
            }
            uint32_t bh_[4][2], bl_[4][2];
            #pragma unroll
            for (int j = 0; j < 4; j++) {
                int nb = wn * 32 + j * 8 + g;
                bh_[j][0] = __float_as_uint(Bhb[nb * BSTR + ks + q]);
                bh_[j][1] = __float_as_uint(Bhb[nb * BSTR + ks + q + 4]);
                bl_[j][0] = __float_as_uint(Blb[nb * BSTR + ks + q]);
                bl_[j][1] = __float_as_uint(Blb[nb * BSTR + ks + q + 4]);
            }
            #pragma unroll
            for (int i = 0; i < 2; i++)
                #pragma unroll
                for (int j = 0; j < 4; j++) {
                    MMA_TF32(acc[i][j], ah[i][0], ah[i][1], ah[i][2], ah[i][3], bh_[j][0], bh_[j][1]);
                    MMA_TF32(acc[i][j], al[i][0], al[i][1], al[i][2], al[i][3], bh_[j][0], bh_[j][1]);
                    MMA_TF32(acc[i][j], ah[i][0], ah[i][1], ah[i][2], ah[i][3], bl_[j][0], bl_[j][1]);
                }
        }
        __syncthreads();
    }

    // ---- store C ----
    #pragma unroll
    for (int i = 0; i < 2; i++) {
        int r0 = blockRow + wm * 32 + i * 16 + g;
        int r1 = r0 + 8;
        #pragma unroll
        for (int j = 0; j < 4; j++) {
            int c = blockCol + wn * 32 + j * 8 + q * 2;
            if (r0 < M) *(float2*)(C + (size_t)r0 * Nc + c) = make_float2(acc[i][j][0], acc[i][j][1]);
            if (r1 < M) *(float2*)(C + (size_t)r1 * Nc + c) = make_float2(acc[i][j][2], acc[i][j][3]);
        }
    }

    // ---- fused el/er epilogue (per-row dot with attn over this 64-col tile) ----
    float pl[2][2] = {{0.f, 0.f}, {0.f, 0.f}};
    float pr[2][2] = {{0.f, 0.f}, {0.f, 0.f}};
    #pragma unroll
    for (int j = 0; j < 4; j++) {
        int idx = blockCol + wn * 32 + j * 8 + q * 2;
        float a0 = __ldg(&attn_l[idx]), a1 = __ldg(&attn_l[idx + 1]);
        float b0 = __ldg(&attn_r[idx]), b1 = __ldg(&attn_r[idx + 1]);
        #pragma unroll
        for (int i = 0; i < 2; i++) {
            pl[i][0] += acc[i][j][0] * a0 + acc[i][j][1] * a1;
            pl[i][1] += acc[i][j][2] * a0 + acc[i][j][3] * a1;
            pr[i][0] += acc[i][j][0] * b0 + acc[i][j][1] * b1;
            pr[i][1] += acc[i][j][2] * b0 + acc[i][j][3] * b1;
        }
    }
    #pragma unroll
    for (int off = 1; off <= 2; off <<= 1) {
        #pragma unroll
        for (int i = 0; i < 2; i++) {
            pl[i][0] += __shfl_xor_sync(0xffffffffu, pl[i][0], off);
            pl[i][1] += __shfl_xor_sync(0xffffffffu, pl[i][1], off);
            pr[i][0] += __shfl_xor_sync(0xffffffffu, pr[i][0], off);
            pr[i][1] += __shfl_xor_sync(0xffffffffu, pr[i][1], off);
        }
    }
    if (wn == 0 && q == 0) {
        #pragma unroll
        for (int i = 0; i < 2; i++) {
            int row = wm * 32 + i * 16 + g;
            s_el[row]     = pl[i][0];  s_el[row + 8] = pl[i][1];
            s_er[row]     = pr[i][0];  s_er[row + 8] = pr[i][1];
        }
    }
    __syncthreads();
    if (wn == 1 && q == 0) {
        #pragma unroll
        for (int i = 0; i < 2; i++) {
            #pragma unroll
            for (int h8 = 0; h8 < 2; h8++) {
                int row = wm * 32 + i * 16 + g + h8 * 8;
                int r = blockRow + row;
                if (r < M) {
                    float vl = pl[i][h8] + s_el[row];
                    float vr = pr[i][h8] + s_er[row];
                    if (HEADS == 1) {
                        el[(size_t)blockIdx.x * M + r] = vl;   // partials, summed in agg2
                        er[(size_t)blockIdx.x * M + r] = vr;
                    } else {
                        el[(size_t)r * HEADS + blockIdx.x] = vl;
                        er[(size_t)r * HEADS + blockIdx.x] = vr;
                    }
                }
            }
        }
    }
}

// ---------------- fused softmax + aggregation ----------------
__device__ __forceinline__ float leaky_exp(float e) {
    e = (e > 0.f) ? e : NEG_SLOPE * e;
    return __expf(e);
}

// layer 1: H=4, D=64, C=256. One warp per node.
__global__ __launch_bounds__(256) void aggregate1_kernel(
    const float* __restrict__ ft, const float* __restrict__ el, const float* __restrict__ er,
    const int* __restrict__ rowptr, const int* __restrict__ colsrc,
    const float* __restrict__ bias, float* __restrict__ out, int Nn)
{
    int warp = threadIdx.x >> 5, lane = threadIdx.x & 31;
    int n = blockIdx.x * 8 + warp;
    if (n >= Nn) return;
    int start = rowptr[n];
    int deg = rowptr[n + 1] - start;

    const bool hlo = (lane < 16);
    float4 er4 = __ldg((const float4*)(er + (size_t)n * 4));
    float erA = hlo ? er4.x : er4.y;
    float erB = hlo ? er4.z : er4.w;

    float4 accA = make_float4(0.f, 0.f, 0.f, 0.f);
    float4 accB = make_float4(0.f, 0.f, 0.f, 0.f);
    float wsumA = 0.f, wsumB = 0.f;
    const float* ftA = ft + lane * 4;
    const float* ftB = ft + 128 + lane * 4;

    int k = 0;
    for (; k + 4 <= deg; k += 4) {
        int s0 = __ldg(&colsrc[start + k + 0]);
        int s1 = __ldg(&colsrc[start + k + 1]);
        int s2 = __ldg(&colsrc[start + k + 2]);
        int s3 = __ldg(&colsrc[start + k + 3]);
        float4 l0 = __ldg((const float4*)(el + (size_t)s0 * 4));
        float4 l1 = __ldg((const float4*)(el + (size_t)s1 * 4));
        float4 l2 = __ldg((const float4*)(el + (size_t)s2 * 4));
        float4 l3 = __ldg((const float4*)(el + (size_t)s3 * 4));
        float4 fA0 = *(const float4*)(ftA + (size_t)s0 * 256);
        float4 fB0 = *(const float4*)(ftB + (size_t)s0 * 256);
        float4 fA1 = *(const float4*)(ftA + (size_t)s1 * 256);
        float4 fB1 = *(const float4*)(ftB + (size_t)s1 * 256);
        float4 fA2 = *(const float4*)(ftA + (size_t)s2 * 256);
        float4 fB2 = *(const float4*)(ftB + (size_t)s2 * 256);
        float4 fA3 = *(const float4*)(ftA + (size_t)s3 * 256);
        float4 fB3 = *(const float4*)(ftB + (size_t)s3 * 256);
        float wA0 = leaky_exp((hlo ? l0.x : l0.y) + erA);
        float wB0 = leaky_exp((hlo ? l0.z : l0.w) + erB);
        float wA1 = leaky_exp((hlo ? l1.x : l1.y) + erA);
        float wB1 = leaky_exp((hlo ? l1.z : l1.w) + erB);
        float wA2 = leaky_exp((hlo ? l2.x : l2.y) + erA);
        float wB2 = leaky_exp((hlo ? l2.z : l2.w) + erB);
        float wA3 = leaky_exp((hlo ? l3.x : l3.y) + erA);
        float wB3 = leaky_exp((hlo ? l3.z : l3.w) + erB);
        accA.x += wA0 * fA0.x + wA1 * fA1.x + wA2 * fA2.x + wA3 * fA3.x;
        accA.y += wA0 * fA0.y + wA1 * fA1.y + wA2 * fA2.y + wA3 * fA3.y;
        accA.z += wA0 * fA0.z + wA1 * fA1.z + wA2 * fA2.z + wA3 * fA3.z;
        accA.w += wA0 * fA0.w + wA1 * fA1.w + wA2 * fA2.w + wA3 * fA3.w;
        accB.x += wB0 * fB0.x + wB1 * fB1.x + wB2 * fB2.x + wB3 * fB3.x;
        accB.y += wB0 * fB0.y + wB1 * fB1.y + wB2 * fB2.y + wB3 * fB3.y;
        accB.z += wB0 * fB0.z + wB1 * fB1.z + wB2 * fB2.z + wB3 * fB3.z;
        accB.w += wB0 * fB0.w + wB1 * fB1.w + wB2 * fB2.w + wB3 * fB3.w;
        wsumA += (wA0 + wA1) + (wA2 + wA3);
        wsumB += (wB0 + wB1) + (wB2 + wB3);
    }
    for (; k < deg; k++) {
        int s0 = __ldg(&colsrc[start + k]);
        float4 l0 = __ldg((const float4*)(el + (size_t)s0 * 4));
        float4 fA0 = *(const float4*)(ftA + (size_t)s0 * 256);
        float4 fB0 = *(const float4*)(ftB + (size_t)s0 * 256);
        float wA0 = leaky_exp((hlo ? l0.x : l0.y) + erA);
        float wB0 = leaky_exp((hlo ? l0.z : l0.w) + erB);
        accA.x += wA0 * fA0.x; accA.y += wA0 * fA0.y;
        accA.z += wA0 * fA0.z; accA.w += wA0 * fA0.w;
        accB.x += wB0 * fB0.x; accB.y += wB0 * fB0.y;
        accB.z += wB0 * fB0.z; accB.w += wB0 * fB0.w;
        wsumA += wA0; wsumB += wB0;
    }

    float invA = (deg > 0) ? (1.f / wsumA) : 0.f;
    float invB = (deg > 0) ? (1.f / wsumB) : 0.f;
    float4 bA = __ldg((const float4*)(bias + lane * 4));
    float4 bB = __ldg((const float4*)(bias + 128 + lane * 4));
    float4 oA, oB;
    oA.x = fmaxf(accA.x * invA + bA.x, 0.f);
    oA.y = fmaxf(accA.y * invA + bA.y, 0.f);
    oA.z = fmaxf(accA.z * invA + bA.z, 0.f);
    oA.w = fmaxf(accA.w * invA + bA.w, 0.f);
    oB.x = fmaxf(accB.x * invB + bB.x, 0.f);
    oB.y = fmaxf(accB.y * invB + bB.y, 0.f);
    oB.z = fmaxf(accB.z * invB + bB.z, 0.f);
    oB.w = fmaxf(accB.w * invB + bB.w, 0.f);
    *(float4*)(out + (size_t)n * 256 + lane * 4) = oA;
    *(float4*)(out + (size_t)n * 256 + 128 + lane * 4) = oB;
}

// layer 2: H=1, D=128. el/er arrive as two partial arrays [2][Nn].
__global__ __launch_bounds__(256) void aggregate2_kernel(
    const float* __restrict__ ft, const float* __restrict__ elp, const float* __restrict__ erp,
    const int* __restrict__ rowptr, const int* __restrict__ colsrc,
    const float* __restrict__ bias, float* __restrict__ out, int Nn)
{
    int warp = threadIdx.x >> 5, lane = threadIdx.x & 31;
    int n = blockIdx.x * 8 + warp;
    if (n >= Nn) return;
    int start = rowptr[n];
    int deg = rowptr[n + 1] - start;

    float er_n = __ldg(&erp[n]) + __ldg(&erp[Nn + n]);
    float4 acc = make_float4(0.f, 0.f, 0.f, 0.f);
    float wsum = 0.f;
    const float* ftp = ft + lane * 4;

    int k = 0;
    for (; k + 8 <= deg; k += 8) {
        int s[8];
        #pragma unroll
        for (int u = 0; u < 8; u++) s[u] = __ldg(&colsrc[start + k + u]);
        float e[8];
        #pragma unroll
        for (int u = 0; u < 8; u++) e[u] = __ldg(&elp[s[u]]) + __ldg(&elp[Nn + s[u]]);
        float4 f[8];
        #pragma unroll
        for (int u = 0; u < 8; u++) f[u] = *(const float4*)(ftp + (size_t)s[u] * 128);
        #pragma unroll
        for (int u = 0; u < 8; u++) {
            float w = leaky_exp(e[u] + er_n);
            acc.x += w * f[u].x; acc.y += w * f[u].y;
            acc.z += w * f[u].z; acc.w += w * f[u].w;
            wsum += w;
        }
    }
    for (; k < deg; k++) {
        int s0 = __ldg(&colsrc[start + k]);
        float w = leaky_exp(__ldg(&elp[s0]) + __ldg(&elp[Nn + s0]) + er_n);
        float4 f0 = *(const float4*)(ftp + (size_t)s0 * 128);
        acc.x += w * f0.x; acc.y += w * f0.y;
        acc.z += w * f0.z; acc.w += w * f0.w;
        wsum += w;
    }

    float inv = (deg > 0) ? (1.f / wsum) : 0.f;
    float4 b = __ldg((const float4*)(bias + lane * 4));
    float4 o;
    o.x = acc.x * inv + b.x;
    o.y = acc.y * inv + b.y;
    o.z = acc.z * inv + b.z;
    o.w = acc.w * inv + b.w;
    *(float4*)(out + (size_t)n * 128 + lane * 4) = o;
}

// ---------------- launch ----------------
extern "C" void kernel_launch(void* const* d_in, const int* in_sizes, int n_in,
                              void* d_out, int out_size)
{
    const float* feat    = (const float*)d_in[0];
    const int*   src     = (const int*)  d_in[1];
    const int*   dst     = (const int*)  d_in[2];
    const float* W1      = (const float*)d_in[3];
    const float* attn_l1 = (const float*)d_in[4];
    const float* attn_r1 = (const float*)d_in[5];
    const float* bias1   = (const float*)d_in[6];
    const float* W2      = (const float*)d_in[7];
    const float* attn_l2 = (const float*)d_in[8];
    const float* attn_r2 = (const float*)d_in[9];
    const float* bias2   = (const float*)d_in[10];
    float* out = (float*)d_out;

    float *ft1, *h1, *el1, *er1, *ft2, *el2p, *er2p;
    float *wt1h, *wt1l, *wt2h, *wt2l;
    int *cnt, *rowptr, *colsrc;
    cudaGetSymbolAddress((void**)&ft1,    g_ft1);
    cudaGetSymbolAddress((void**)&h1,     g_h1);
    cudaGetSymbolAddress((void**)&el1,    g_el1);
    cudaGetSymbolAddress((void**)&er1,    g_er1);
    cudaGetSymbolAddress((void**)&ft2,    g_ft2);
    cudaGetSymbolAddress((void**)&el2p,   g_el2p);
    cudaGetSymbolAddress((void**)&er2p,   g_er2p);
    cudaGetSymbolAddress((void**)&wt1h,   g_wt1h);
    cudaGetSymbolAddress((void**)&wt1l,   g_wt1l);
    cudaGetSymbolAddress((void**)&wt2h,   g_wt2h);
    cudaGetSymbolAddress((void**)&wt2l,   g_wt2l);
    cudaGetSymbolAddress((void**)&cnt,    g_cnt);
    cudaGetSymbolAddress((void**)&rowptr, g_rowptr);
    cudaGetSymbolAddress((void**)&colsrc, g_colsrc);

    // dyn smem: A raw 2*128*36 + B hi/lo 2*2*64*36 + el/er 256 floats
    const int SMEM_SZ = (2 * 128 * 36 + 2 * 64 * 36 * 2 + 256) * 4;
    static bool attr_set = false;
    if (!attr_set) {
        cudaFuncSetAttribute(mma_gemm_db_kernel<4>, cudaFuncAttributeMaxDynamicSharedMemorySize, SMEM_SZ);
        cudaFuncSetAttribute(mma_gemm_db_kernel<1>, cudaFuncAttributeMaxDynamicSharedMemorySize, SMEM_SZ);
        attr_set = true;
    }

    transpose_split_kernel<<<384, 256>>>(W1, W2, wt1h, wt1l, wt2h, wt2l);          // 1
    {                                                                              // 2: gemm1
        dim3 grid(4, (N_NODES + 127) / 128);
        mma_gemm_db_kernel<4><<<grid, 256, SMEM_SZ>>>(feat, wt1h, wt1l, ft1,
                                                      attn_l1, attn_r1, el1, er1,
                                                      N_NODES, 256);
    }
    zero_int_kernel<<<256, 256>>>(cnt, N_NODES);                                   // 3
    count_dst_kernel<<<2048, 256>>>(dst, cnt, N_EDGES);                            // 4
    scan_kernel<<<1, 1024>>>(cnt, rowptr, N_NODES);                                // 5
    scatter_kernel<<<2048, 256>>>(src, dst, rowptr, cnt, colsrc, N_EDGES);         // 6
    aggregate1_kernel<<<(N_NODES + 7) / 8, 256>>>(ft1, el1, er1, rowptr, colsrc,   // 7
                                                  bias1, h1, N_NODES);
    {                                                                              // 8: gemm2
        dim3 grid(2, (N_NODES + 127) / 128);
        mma_gemm_db_kernel<1><<<grid, 256, SMEM_SZ>>>(h1, wt2h, wt2l, ft2,
                                                      attn_l2, attn_r2, el2p, er2p,
                                                      N_NODES, 128);
    }
    aggregate2_kernel<<<(N_NODES + 7) / 8, 256>>>(ft2, el2p, er2p, rowptr, colsrc, // 9
                                                  bias2, out, N_NODES);
}